// round 1
// baseline (speedup 1.0000x reference)
#include <cuda_runtime.h>
#include <math.h>

// Problem constants
#define BATCH 32
#define SEQ   128
#define WL    20
#define D     300           // D1 = D2 = OUT = 300
#define M_SEQ (BATCH*SEQ*WL)   // 81920 rows of `sequence` flattened
#define M_VEC (BATCH*SEQ)      // 4096 rows of `vector` flattened
#define NEG_INF -1000000000.0f

// Scratch (no cudaMalloc allowed)
__device__ float g_vecpart[M_VEC * D];   // vector @ Wv^T + b
__device__ float g_score[M_SEQ];         // pre-softmax attention scores

// ---------------------------------------------------------------------------
// Kernel 1: vecpart[r][o] = sum_k vector[r][k] * W[o][300+k] + b[o]
// Tiled SGEMM: CTA tile 64(m) x 128(o), 256 threads, 4x8 microtile, K tiles of 16.
// grid = (4096/64, 3)   (o0 = 0,128,256; o tail predicated)
// ---------------------------------------------------------------------------
__global__ __launch_bounds__(256)
void vecpart_kernel(const float* __restrict__ vec,
                    const float* __restrict__ W,
                    const float* __restrict__ bias)
{
    __shared__ float As[16 * 64];    // [k][m]
    __shared__ float Bs[16 * 128];   // [k][o]

    const int tid = threadIdx.x;
    const int tx = tid & 15;         // o direction (16)
    const int ty = tid >> 4;         // m direction (16)
    const int m0 = blockIdx.x * 64;
    const int o0 = blockIdx.y * 128;

    float acc[4][8];
#pragma unroll
    for (int i = 0; i < 4; i++)
#pragma unroll
        for (int j = 0; j < 8; j++) acc[i][j] = 0.f;

    for (int k0 = 0; k0 < D; k0 += 16) {
        // --- load A tile (vector rows), transposed to [k][m] ---
        {
            const int m  = tid >> 2;          // 0..63
            const int kq = (tid & 3) * 4;     // 0,4,8,12
            const float* src = vec + (m0 + m) * D + k0 + kq;
            if (k0 + 16 <= D) {
                float4 a4 = *(const float4*)src;
                As[(kq+0)*64 + m] = a4.x;
                As[(kq+1)*64 + m] = a4.y;
                As[(kq+2)*64 + m] = a4.z;
                As[(kq+3)*64 + m] = a4.w;
            } else {
#pragma unroll
                for (int q = 0; q < 4; q++) {
                    int k = k0 + kq + q;
                    As[(kq+q)*64 + m] = (k < D) ? vec[(m0 + m) * D + k] : 0.f;
                }
            }
        }
        // --- load B tile (Wv rows), transposed to [k][o] ---
        {
            const int o  = tid >> 1;          // 0..127
            const int kq = (tid & 1) * 8;     // 0,8
            const int og = o0 + o;
            if (og < D && k0 + 16 <= D) {
                const float* src = W + (long)og * 600 + 300 + k0 + kq;
                float4 b0 = *(const float4*)src;
                float4 b1 = *(const float4*)(src + 4);
                Bs[(kq+0)*128 + o] = b0.x;
                Bs[(kq+1)*128 + o] = b0.y;
                Bs[(kq+2)*128 + o] = b0.z;
                Bs[(kq+3)*128 + o] = b0.w;
                Bs[(kq+4)*128 + o] = b1.x;
                Bs[(kq+5)*128 + o] = b1.y;
                Bs[(kq+6)*128 + o] = b1.z;
                Bs[(kq+7)*128 + o] = b1.w;
            } else {
#pragma unroll
                for (int q = 0; q < 8; q++) {
                    int k = k0 + kq + q;
                    Bs[(kq+q)*128 + o] =
                        (og < D && k < D) ? W[(long)og * 600 + 300 + k] : 0.f;
                }
            }
        }
        __syncthreads();

#pragma unroll
        for (int kk = 0; kk < 16; kk++) {
            float4 a  = *(const float4*)&As[kk*64  + ty*4];
            float4 b0 = *(const float4*)&Bs[kk*128 + tx*4];
            float4 b1 = *(const float4*)&Bs[kk*128 + 64 + tx*4];
            float av[4] = {a.x, a.y, a.z, a.w};
            float bv[8] = {b0.x, b0.y, b0.z, b0.w, b1.x, b1.y, b1.z, b1.w};
#pragma unroll
            for (int i = 0; i < 4; i++)
#pragma unroll
                for (int j = 0; j < 8; j++) acc[i][j] += av[i] * bv[j];
        }
        __syncthreads();
    }

#pragma unroll
    for (int i = 0; i < 4; i++) {
        int r = m0 + ty*4 + i;
#pragma unroll
        for (int j = 0; j < 8; j++) {
            int o = o0 + ((j < 4) ? (tx*4 + j) : (64 + tx*4 + (j - 4)));
            if (o < D) g_vecpart[(long)r * D + o] = acc[i][j] + __ldg(&bias[o]);
        }
    }
}

// ---------------------------------------------------------------------------
// Kernel 2: score[m] = sum_o tanh( seq[m]·Ws[o] + vecpart[m/20][o] ) * v[o]
// CTA tile: 64 rows of seq; loops over 3 o-passes of 128 cols; accumulates
// per-row score in smem via 16-lane shuffle reduce.
// grid = 81920/64 = 1280 CTAs.
// ---------------------------------------------------------------------------
__global__ __launch_bounds__(256)
void score_kernel(const float* __restrict__ seq,
                  const float* __restrict__ W,
                  const float* __restrict__ v)
{
    __shared__ float As[16 * 64];
    __shared__ float Bs[16 * 128];
    __shared__ float vps[4 * D];     // vecpart rows for the <=4 (b,s) in this tile
    __shared__ float vs[D];
    __shared__ float score_s[64];

    const int tid = threadIdx.x;
    const int tx = tid & 15;
    const int ty = tid >> 4;
    const int m0 = blockIdx.x * 64;
    const int bs0 = m0 / WL;

    // Preload vecpart rows (<=4 distinct (b,s) per 64-row tile) and v
    for (int idx = tid; idx < 4 * D; idx += 256) {
        int r = idx / D, o = idx - r * D;
        int bsg = bs0 + r;
        vps[idx] = (bsg < M_VEC) ? g_vecpart[(long)bsg * D + o] : 0.f;
    }
    for (int idx = tid; idx < D; idx += 256) vs[idx] = v[idx];
    if (tid < 64) score_s[tid] = 0.f;
    __syncthreads();

    for (int o0 = 0; o0 < D; o0 += 128) {
        float acc[4][8];
#pragma unroll
        for (int i = 0; i < 4; i++)
#pragma unroll
            for (int j = 0; j < 8; j++) acc[i][j] = 0.f;

        for (int k0 = 0; k0 < D; k0 += 16) {
            // A tile: seq rows, transposed
            {
                const int m  = tid >> 2;
                const int kq = (tid & 3) * 4;
                const float* src = seq + (long)(m0 + m) * D + k0 + kq;
                if (k0 + 16 <= D) {
                    float4 a4 = *(const float4*)src;
                    As[(kq+0)*64 + m] = a4.x;
                    As[(kq+1)*64 + m] = a4.y;
                    As[(kq+2)*64 + m] = a4.z;
                    As[(kq+3)*64 + m] = a4.w;
                } else {
#pragma unroll
                    for (int q = 0; q < 4; q++) {
                        int k = k0 + kq + q;
                        As[(kq+q)*64 + m] = (k < D) ? seq[(long)(m0 + m) * D + k] : 0.f;
                    }
                }
            }
            // B tile: Ws rows (W[o][0..299]), transposed
            {
                const int o  = tid >> 1;
                const int kq = (tid & 1) * 8;
                const int og = o0 + o;
                if (og < D && k0 + 16 <= D) {
                    const float* src = W + (long)og * 600 + k0 + kq;
                    float4 b0 = *(const float4*)src;
                    float4 b1 = *(const float4*)(src + 4);
                    Bs[(kq+0)*128 + o] = b0.x;
                    Bs[(kq+1)*128 + o] = b0.y;
                    Bs[(kq+2)*128 + o] = b0.z;
                    Bs[(kq+3)*128 + o] = b0.w;
                    Bs[(kq+4)*128 + o] = b1.x;
                    Bs[(kq+5)*128 + o] = b1.y;
                    Bs[(kq+6)*128 + o] = b1.z;
                    Bs[(kq+7)*128 + o] = b1.w;
                } else {
#pragma unroll
                    for (int q = 0; q < 8; q++) {
                        int k = k0 + kq + q;
                        Bs[(kq+q)*128 + o] =
                            (og < D && k < D) ? W[(long)og * 600 + k] : 0.f;
                    }
                }
            }
            __syncthreads();

#pragma unroll
            for (int kk = 0; kk < 16; kk++) {
                float4 a  = *(const float4*)&As[kk*64  + ty*4];
                float4 b0 = *(const float4*)&Bs[kk*128 + tx*4];
                float4 b1 = *(const float4*)&Bs[kk*128 + 64 + tx*4];
                float av[4] = {a.x, a.y, a.z, a.w};
                float bv[8] = {b0.x, b0.y, b0.z, b0.w, b1.x, b1.y, b1.z, b1.w};
#pragma unroll
                for (int i = 0; i < 4; i++)
#pragma unroll
                    for (int j = 0; j < 8; j++) acc[i][j] += av[i] * bv[j];
            }
            __syncthreads();
        }

        // Epilogue: tanh(lin)*v, reduce over the 128 o's of this pass
#pragma unroll
        for (int i = 0; i < 4; i++) {
            int row = ty*4 + i;
            int bsl = (m0 + row) / WL - bs0;
            float p = 0.f;
#pragma unroll
            for (int j = 0; j < 8; j++) {
                int o = o0 + ((j < 4) ? (tx*4 + j) : (64 + tx*4 + (j - 4)));
                if (o < D) {
                    float lin = acc[i][j] + vps[bsl * D + o];
                    p += tanhf(lin) * vs[o];
                }
            }
#pragma unroll
            for (int off = 8; off > 0; off >>= 1)
                p += __shfl_down_sync(0xffffffffu, p, off, 16);
            if (tx == 0) score_s[row] += p;
        }
        __syncthreads();
    }

    if (tid < 64) g_score[m0 + tid] = score_s[tid];
}

// ---------------------------------------------------------------------------
// Kernel 3: masked softmax over w (20) + weighted = alphas · seq
// grid = 4096 (one CTA per (b,s)), block 128.
// ---------------------------------------------------------------------------
__global__ __launch_bounds__(128)
void softmax_weighted_kernel(const float* __restrict__ seq,
                             const int* __restrict__ masks,
                             float* __restrict__ out)
{
    const int bs = blockIdx.x;
    const int t = threadIdx.x;
    __shared__ float al[WL];

    if (t == 0) {
        float sc[WL];
        float mx = -1e30f;
#pragma unroll
        for (int w = 0; w < WL; w++) {
            float s = g_score[bs * WL + w];
            s = (masks[bs * WL + w] == 0) ? NEG_INF : s;
            sc[w] = s;
            mx = fmaxf(mx, s);
        }
        float sum = 0.f;
#pragma unroll
        for (int w = 0; w < WL; w++) {
            float e = expf(sc[w] - mx);
            al[w] = e;
            sum += e;
        }
        float inv = 1.f / sum;
#pragma unroll
        for (int w = 0; w < WL; w++) al[w] *= inv;
    }
    __syncthreads();

    const float* base = seq + (long)bs * WL * D;
    for (int d = t; d < D; d += 128) {
        float a = 0.f;
#pragma unroll
        for (int w = 0; w < WL; w++) a += al[w] * base[w * D + d];
        out[(long)bs * D + d] = a;
    }
}

// ---------------------------------------------------------------------------
extern "C" void kernel_launch(void* const* d_in, const int* in_sizes, int n_in,
                              void* d_out, int out_size)
{
    const float* seq   = (const float*)d_in[0];   // (32,128,20,300)
    const float* vec   = (const float*)d_in[1];   // (32,128,300)
    const int*   masks = (const int*)  d_in[2];   // (32,128,20)
    const float* W     = (const float*)d_in[3];   // (300,600)
    const float* bias  = (const float*)d_in[4];   // (300,)
    const float* v     = (const float*)d_in[5];   // (300,)
    float* out = (float*)d_out;                   // (32,128,300)

    vecpart_kernel<<<dim3(M_VEC / 64, 3), 256>>>(vec, W, bias);
    score_kernel<<<dim3(M_SEQ / 64), 256>>>(seq, W, v);
    softmax_weighted_kernel<<<M_VEC, 128>>>(seq, masks, out);
}

// round 2
// speedup vs baseline: 1.0339x; 1.0339x over previous
#include <cuda_runtime.h>
#include <math.h>

// Problem constants
#define BATCH 32
#define SEQ   128
#define WL    20
#define D     300           // D1 = D2 = OUT = 300
#define M_SEQ (BATCH*SEQ*WL)   // 81920 rows of `sequence` flattened
#define M_VEC (BATCH*SEQ)      // 4096 rows of `vector` flattened
#define NEG_INF -1000000000.0f

// Scratch (no cudaMalloc allowed)
__device__ float g_vecpart[M_VEC * D];   // vector @ Wv^T + b
__device__ float g_score[M_SEQ];         // pre-softmax attention scores

// ---------------------------------------------------------------------------
// Packed fp32x2 helpers (sm_103a FFMA2 — only reachable via PTX fma.rn.f32x2)
// ---------------------------------------------------------------------------
__device__ __forceinline__ unsigned long long pack_dup(float x) {
    unsigned long long r;
    asm("mov.b64 %0, {%1, %1};" : "=l"(r) : "f"(x));
    return r;
}
__device__ __forceinline__ void ffma2(unsigned long long &acc,
                                      unsigned long long a,
                                      unsigned long long b) {
    asm("fma.rn.f32x2 %0, %1, %2, %0;" : "+l"(acc) : "l"(a), "l"(b));
}
__device__ __forceinline__ void unpack2(unsigned long long p, float &lo, float &hi) {
    asm("mov.b64 {%0, %1}, %2;" : "=f"(lo), "=f"(hi) : "l"(p));
}

// ---------------------------------------------------------------------------
// Kernel 1: vecpart[r][o] = sum_k vector[r][k] * W[o][300+k] + b[o]
// CTA tile 64(m) x 128(o), 256 threads, 4x8 microtile (packed 4x4xf32x2).
// grid = (4096/64, 3)
// ---------------------------------------------------------------------------
__global__ __launch_bounds__(256)
void vecpart_kernel(const float* __restrict__ vec,
                    const float* __restrict__ W,
                    const float* __restrict__ bias)
{
    __shared__ float As[16 * 64];    // [k][m]
    __shared__ float Bs[16 * 128];   // [k][o]

    const int tid = threadIdx.x;
    const int tx = tid & 15;         // o direction (16)
    const int ty = tid >> 4;         // m direction (16)
    const int m0 = blockIdx.x * 64;
    const int o0 = blockIdx.y * 128;

    unsigned long long acc[4][4];
#pragma unroll
    for (int i = 0; i < 4; i++)
#pragma unroll
        for (int j = 0; j < 4; j++) acc[i][j] = 0ull;

    for (int k0 = 0; k0 < D; k0 += 16) {
        // A tile (vector rows), transposed to [k][m]
        {
            const int m  = tid >> 2;
            const int kq = (tid & 3) * 4;
            const float* src = vec + (m0 + m) * D + k0 + kq;
            if (k0 + 16 <= D) {
                float4 a4 = *(const float4*)src;
                As[(kq+0)*64 + m] = a4.x;
                As[(kq+1)*64 + m] = a4.y;
                As[(kq+2)*64 + m] = a4.z;
                As[(kq+3)*64 + m] = a4.w;
            } else {
#pragma unroll
                for (int q = 0; q < 4; q++) {
                    int k = k0 + kq + q;
                    As[(kq+q)*64 + m] = (k < D) ? vec[(m0 + m) * D + k] : 0.f;
                }
            }
        }
        // B tile (Wv rows), transposed to [k][o]
        {
            const int o  = tid >> 1;
            const int kq = (tid & 1) * 8;
            const int og = o0 + o;
            if (og < D && k0 + 16 <= D) {
                const float* src = W + (long)og * 600 + 300 + k0 + kq;
                float4 b0 = *(const float4*)src;
                float4 b1 = *(const float4*)(src + 4);
                Bs[(kq+0)*128 + o] = b0.x;
                Bs[(kq+1)*128 + o] = b0.y;
                Bs[(kq+2)*128 + o] = b0.z;
                Bs[(kq+3)*128 + o] = b0.w;
                Bs[(kq+4)*128 + o] = b1.x;
                Bs[(kq+5)*128 + o] = b1.y;
                Bs[(kq+6)*128 + o] = b1.z;
                Bs[(kq+7)*128 + o] = b1.w;
            } else {
#pragma unroll
                for (int q = 0; q < 8; q++) {
                    int k = k0 + kq + q;
                    Bs[(kq+q)*128 + o] =
                        (og < D && k < D) ? W[(long)og * 600 + 300 + k] : 0.f;
                }
            }
        }
        __syncthreads();

#pragma unroll
        for (int kk = 0; kk < 16; kk++) {
            float4 a = *(const float4*)&As[kk*64 + ty*4];
            ulonglong2 bp0 = *(const ulonglong2*)&Bs[kk*128 + tx*4];
            ulonglong2 bp1 = *(const ulonglong2*)&Bs[kk*128 + 64 + tx*4];
            float av[4] = {a.x, a.y, a.z, a.w};
#pragma unroll
            for (int i = 0; i < 4; i++) {
                unsigned long long ad = pack_dup(av[i]);
                ffma2(acc[i][0], ad, bp0.x);
                ffma2(acc[i][1], ad, bp0.y);
                ffma2(acc[i][2], ad, bp1.x);
                ffma2(acc[i][3], ad, bp1.y);
            }
        }
        __syncthreads();
    }

#pragma unroll
    for (int i = 0; i < 4; i++) {
        int r = m0 + ty*4 + i;
#pragma unroll
        for (int j = 0; j < 4; j++) {
            float lo, hi;
            unpack2(acc[i][j], lo, hi);
            int obase = o0 + ((j < 2) ? (tx*4 + 2*j) : (64 + tx*4 + 2*(j-2)));
            if (obase < D)     g_vecpart[(long)r * D + obase]     = lo + __ldg(&bias[obase]);
            if (obase + 1 < D) g_vecpart[(long)r * D + obase + 1] = hi + __ldg(&bias[obase+1]);
        }
    }
}

// ---------------------------------------------------------------------------
// Kernel 2: score[m] = sum_o tanh( seq[m]·Ws[o] + vecpart[m/20][o] ) * v[o]
// CTA tile: 64 rows of seq; 3 o-passes of 128 cols; packed FFMA2 mainloop.
// grid = 81920/64 = 1280 CTAs.
// ---------------------------------------------------------------------------
__global__ __launch_bounds__(256)
void score_kernel(const float* __restrict__ seq,
                  const float* __restrict__ W,
                  const float* __restrict__ v)
{
    __shared__ float As[16 * 64];
    __shared__ float Bs[16 * 128];
    __shared__ float vps[4 * D];     // vecpart rows for the <=4 (b,s) in this tile
    __shared__ float vs[D];
    __shared__ float score_s[64];

    const int tid = threadIdx.x;
    const int tx = tid & 15;
    const int ty = tid >> 4;
    const int m0 = blockIdx.x * 64;
    const int bs0 = m0 / WL;

    for (int idx = tid; idx < 4 * D; idx += 256) {
        int r = idx / D, o = idx - r * D;
        int bsg = bs0 + r;
        vps[idx] = (bsg < M_VEC) ? g_vecpart[(long)bsg * D + o] : 0.f;
    }
    for (int idx = tid; idx < D; idx += 256) vs[idx] = v[idx];
    if (tid < 64) score_s[tid] = 0.f;
    __syncthreads();

    for (int o0 = 0; o0 < D; o0 += 128) {
        unsigned long long acc[4][4];
#pragma unroll
        for (int i = 0; i < 4; i++)
#pragma unroll
            for (int j = 0; j < 4; j++) acc[i][j] = 0ull;

        for (int k0 = 0; k0 < D; k0 += 16) {
            // A tile: seq rows, transposed
            {
                const int m  = tid >> 2;
                const int kq = (tid & 3) * 4;
                const float* src = seq + (long)(m0 + m) * D + k0 + kq;
                if (k0 + 16 <= D) {
                    float4 a4 = *(const float4*)src;
                    As[(kq+0)*64 + m] = a4.x;
                    As[(kq+1)*64 + m] = a4.y;
                    As[(kq+2)*64 + m] = a4.z;
                    As[(kq+3)*64 + m] = a4.w;
                } else {
#pragma unroll
                    for (int q = 0; q < 4; q++) {
                        int k = k0 + kq + q;
                        As[(kq+q)*64 + m] = (k < D) ? seq[(long)(m0 + m) * D + k] : 0.f;
                    }
                }
            }
            // B tile: Ws rows (W[o][0..299]), transposed
            {
                const int o  = tid >> 1;
                const int kq = (tid & 1) * 8;
                const int og = o0 + o;
                if (og < D && k0 + 16 <= D) {
                    const float* src = W + (long)og * 600 + k0 + kq;
                    float4 b0 = *(const float4*)src;
                    float4 b1 = *(const float4*)(src + 4);
                    Bs[(kq+0)*128 + o] = b0.x;
                    Bs[(kq+1)*128 + o] = b0.y;
                    Bs[(kq+2)*128 + o] = b0.z;
                    Bs[(kq+3)*128 + o] = b0.w;
                    Bs[(kq+4)*128 + o] = b1.x;
                    Bs[(kq+5)*128 + o] = b1.y;
                    Bs[(kq+6)*128 + o] = b1.z;
                    Bs[(kq+7)*128 + o] = b1.w;
                } else {
#pragma unroll
                    for (int q = 0; q < 8; q++) {
                        int k = k0 + kq + q;
                        Bs[(kq+q)*128 + o] =
                            (og < D && k < D) ? W[(long)og * 600 + k] : 0.f;
                    }
                }
            }
            __syncthreads();

#pragma unroll
            for (int kk = 0; kk < 16; kk++) {
                float4 a = *(const float4*)&As[kk*64 + ty*4];
                ulonglong2 bp0 = *(const ulonglong2*)&Bs[kk*128 + tx*4];
                ulonglong2 bp1 = *(const ulonglong2*)&Bs[kk*128 + 64 + tx*4];
                float av[4] = {a.x, a.y, a.z, a.w};
#pragma unroll
                for (int i = 0; i < 4; i++) {
                    unsigned long long ad = pack_dup(av[i]);
                    ffma2(acc[i][0], ad, bp0.x);
                    ffma2(acc[i][1], ad, bp0.y);
                    ffma2(acc[i][2], ad, bp1.x);
                    ffma2(acc[i][3], ad, bp1.y);
                }
            }
            __syncthreads();
        }

        // Epilogue: tanh(lin)*v, reduce over the 128 o's of this pass
#pragma unroll
        for (int i = 0; i < 4; i++) {
            int row = ty*4 + i;
            int bsl = (m0 + row) / WL - bs0;
            float p = 0.f;
#pragma unroll
            for (int j = 0; j < 4; j++) {
                float lo, hi;
                unpack2(acc[i][j], lo, hi);
                int obase = o0 + ((j < 2) ? (tx*4 + 2*j) : (64 + tx*4 + 2*(j-2)));
                if (obase < D) {
                    float lin = lo + vps[bsl * D + obase];
                    p += tanhf(lin) * vs[obase];
                }
                if (obase + 1 < D) {
                    float lin = hi + vps[bsl * D + obase + 1];
                    p += tanhf(lin) * vs[obase + 1];
                }
            }
#pragma unroll
            for (int off = 8; off > 0; off >>= 1)
                p += __shfl_down_sync(0xffffffffu, p, off, 16);
            if (tx == 0) score_s[row] += p;
        }
        __syncthreads();
    }

    if (tid < 64) g_score[m0 + tid] = score_s[tid];
}

// ---------------------------------------------------------------------------
// Kernel 3: masked softmax over w (20) + weighted = alphas · seq
// grid = 4096 (one CTA per (b,s)), block 128.
// ---------------------------------------------------------------------------
__global__ __launch_bounds__(128)
void softmax_weighted_kernel(const float* __restrict__ seq,
                             const int* __restrict__ masks,
                             float* __restrict__ out)
{
    const int bs = blockIdx.x;
    const int t = threadIdx.x;
    __shared__ float al[WL];

    if (t == 0) {
        float sc[WL];
        float mx = -1e30f;
#pragma unroll
        for (int w = 0; w < WL; w++) {
            float s = g_score[bs * WL + w];
            s = (masks[bs * WL + w] == 0) ? NEG_INF : s;
            sc[w] = s;
            mx = fmaxf(mx, s);
        }
        float sum = 0.f;
#pragma unroll
        for (int w = 0; w < WL; w++) {
            float e = expf(sc[w] - mx);
            al[w] = e;
            sum += e;
        }
        float inv = 1.f / sum;
#pragma unroll
        for (int w = 0; w < WL; w++) al[w] *= inv;
    }
    __syncthreads();

    const float* base = seq + (long)bs * WL * D;
    for (int d = t; d < D; d += 128) {
        float a = 0.f;
#pragma unroll
        for (int w = 0; w < WL; w++) a += al[w] * base[w * D + d];
        out[(long)bs * D + d] = a;
    }
}

// ---------------------------------------------------------------------------
extern "C" void kernel_launch(void* const* d_in, const int* in_sizes, int n_in,
                              void* d_out, int out_size)
{
    const float* seq   = (const float*)d_in[0];   // (32,128,20,300)
    const float* vec   = (const float*)d_in[1];   // (32,128,300)
    const int*   masks = (const int*)  d_in[2];   // (32,128,20)
    const float* W     = (const float*)d_in[3];   // (300,600)
    const float* bias  = (const float*)d_in[4];   // (300,)
    const float* v     = (const float*)d_in[5];   // (300,)
    float* out = (float*)d_out;                   // (32,128,300)

    vecpart_kernel<<<dim3(M_VEC / 64, 3), 256>>>(vec, W, bias);
    score_kernel<<<dim3(M_SEQ / 64), 256>>>(seq, W, v);
    softmax_weighted_kernel<<<M_VEC, 128>>>(seq, masks, out);
}

// round 4
// speedup vs baseline: 1.5536x; 1.5026x over previous
#include <cuda_runtime.h>
#include <cuda_bf16.h>
#include <math.h>
#include <stdint.h>

// Problem constants
#define BATCH 32
#define SEQ   128
#define WL    20
#define D     300
#define DPAD  320                 // padded O and K dims
#define M_SEQ (BATCH*SEQ*WL)      // 81920
#define M_VEC (BATCH*SEQ)         // 4096
#define NEG_INF -1000000000.0f

// Scratch (__device__ globals — no cudaMalloc allowed)
__device__ float g_vecpart[M_VEC * D];
__device__ float g_score[M_SEQ];
__device__ __nv_bfloat16 g_Whi[DPAD * DPAD];       // Ws split hi, [o][k], padded
__device__ __nv_bfloat16 g_Wlo[DPAD * DPAD];       // Ws split lo
__device__ __nv_bfloat16 g_seq_hi[(size_t)M_SEQ * DPAD];  // seq split hi, padded K
__device__ __nv_bfloat16 g_seq_lo[(size_t)M_SEQ * DPAD];

// ---------------------------------------------------------------------------
// Warp-MMA helpers (sm_80-era PTX: valid at plain sm_103 target)
// ---------------------------------------------------------------------------
__device__ __forceinline__ uint32_t smem_u32(const void* p) {
    uint32_t a;
    asm("{ .reg .u64 t; cvta.to.shared.u64 t, %1; cvt.u32.u64 %0, t; }" : "=r"(a) : "l"(p));
    return a;
}
__device__ __forceinline__ void ldsm_x4(uint32_t* r, uint32_t addr) {
    asm volatile("ldmatrix.sync.aligned.m8n8.x4.shared.b16 {%0,%1,%2,%3}, [%4];"
                 : "=r"(r[0]), "=r"(r[1]), "=r"(r[2]), "=r"(r[3]) : "r"(addr));
}
__device__ __forceinline__ void mma16816(float* c, const uint32_t* a, const uint32_t* b) {
    asm volatile("mma.sync.aligned.m16n8k16.row.col.f32.bf16.bf16.f32 "
                 "{%0,%1,%2,%3}, {%4,%5,%6,%7}, {%8,%9}, {%0,%1,%2,%3};"
                 : "+f"(c[0]), "+f"(c[1]), "+f"(c[2]), "+f"(c[3])
                 : "r"(a[0]), "r"(a[1]), "r"(a[2]), "r"(a[3]), "r"(b[0]), "r"(b[1]));
}

// ---------------------------------------------------------------------------
// Prep: split W[:, :300] (Ws) into bf16 hi/lo, zero-padded to 320x320
// ---------------------------------------------------------------------------
__global__ __launch_bounds__(256)
void prep_w_kernel(const float* __restrict__ W)
{
    int idx = blockIdx.x * 256 + threadIdx.x;
    if (idx >= DPAD * DPAD) return;
    int o = idx / DPAD, k = idx - o * DPAD;
    float x = (o < D && k < D) ? W[(long)o * 600 + k] : 0.f;
    __nv_bfloat16 hi = __float2bfloat16_rn(x);
    __nv_bfloat16 lo = __float2bfloat16_rn(x - __bfloat162float(hi));
    g_Whi[idx] = hi;
    g_Wlo[idx] = lo;
}

// ---------------------------------------------------------------------------
// Prep: split seq (81920 x 300) into bf16 hi/lo, zero-padded K to 320
// one thread = 4 consecutive k
// ---------------------------------------------------------------------------
__global__ __launch_bounds__(256)
void prep_seq_kernel(const float* __restrict__ seq)
{
    size_t gid = (size_t)blockIdx.x * 256 + threadIdx.x;
    if (gid >= (size_t)M_SEQ * (DPAD / 4)) return;
    size_t row = gid / (DPAD / 4);
    int k4 = (int)(gid % (DPAD / 4));
    float4 x = make_float4(0.f, 0.f, 0.f, 0.f);
    if (k4 < D / 4)   // 300/4 = 75 exact
        x = *(const float4*)(seq + row * D + k4 * 4);
    __nv_bfloat162 h01 = __floats2bfloat162_rn(x.x, x.y);
    __nv_bfloat162 h23 = __floats2bfloat162_rn(x.z, x.w);
    float2 hf01 = __bfloat1622float2(h01), hf23 = __bfloat1622float2(h23);
    __nv_bfloat162 l01 = __floats2bfloat162_rn(x.x - hf01.x, x.y - hf01.y);
    __nv_bfloat162 l23 = __floats2bfloat162_rn(x.z - hf23.x, x.w - hf23.y);
    size_t off = row * DPAD + k4 * 4;
    *(__nv_bfloat162*)(g_seq_hi + off)     = h01;
    *(__nv_bfloat162*)(g_seq_hi + off + 2) = h23;
    *(__nv_bfloat162*)(g_seq_lo + off)     = l01;
    *(__nv_bfloat162*)(g_seq_lo + off + 2) = l23;
}

// ---------------------------------------------------------------------------
// Kernel 1 (scalar FFMA2): vecpart = vector @ Wv^T + b
// ---------------------------------------------------------------------------
__device__ __forceinline__ unsigned long long pack_dup(float x) {
    unsigned long long r; asm("mov.b64 %0, {%1, %1};" : "=l"(r) : "f"(x)); return r;
}
__device__ __forceinline__ void ffma2(unsigned long long &acc, unsigned long long a, unsigned long long b) {
    asm("fma.rn.f32x2 %0, %1, %2, %0;" : "+l"(acc) : "l"(a), "l"(b));
}
__device__ __forceinline__ void unpack2(unsigned long long p, float &lo, float &hi) {
    asm("mov.b64 {%0, %1}, %2;" : "=f"(lo), "=f"(hi) : "l"(p));
}

__global__ __launch_bounds__(256)
void vecpart_kernel(const float* __restrict__ vec,
                    const float* __restrict__ W,
                    const float* __restrict__ bias)
{
    __shared__ float As[16 * 64];
    __shared__ float Bs[16 * 128];

    const int tid = threadIdx.x;
    const int tx = tid & 15, ty = tid >> 4;
    const int m0 = blockIdx.x * 64, o0 = blockIdx.y * 128;

    unsigned long long acc[4][4];
#pragma unroll
    for (int i = 0; i < 4; i++)
#pragma unroll
        for (int j = 0; j < 4; j++) acc[i][j] = 0ull;

    for (int k0 = 0; k0 < D; k0 += 16) {
        {
            const int m = tid >> 2, kq = (tid & 3) * 4;
            const float* src = vec + (m0 + m) * D + k0 + kq;
            if (k0 + 16 <= D) {
                float4 a4 = *(const float4*)src;
                As[(kq+0)*64 + m] = a4.x; As[(kq+1)*64 + m] = a4.y;
                As[(kq+2)*64 + m] = a4.z; As[(kq+3)*64 + m] = a4.w;
            } else {
#pragma unroll
                for (int q = 0; q < 4; q++) {
                    int k = k0 + kq + q;
                    As[(kq+q)*64 + m] = (k < D) ? vec[(m0 + m) * D + k] : 0.f;
                }
            }
        }
        {
            const int o = tid >> 1, kq = (tid & 1) * 8;
            const int og = o0 + o;
            if (og < D && k0 + 16 <= D) {
                const float* src = W + (long)og * 600 + 300 + k0 + kq;
                float4 b0 = *(const float4*)src, b1 = *(const float4*)(src + 4);
                Bs[(kq+0)*128 + o] = b0.x; Bs[(kq+1)*128 + o] = b0.y;
                Bs[(kq+2)*128 + o] = b0.z; Bs[(kq+3)*128 + o] = b0.w;
                Bs[(kq+4)*128 + o] = b1.x; Bs[(kq+5)*128 + o] = b1.y;
                Bs[(kq+6)*128 + o] = b1.z; Bs[(kq+7)*128 + o] = b1.w;
            } else {
#pragma unroll
                for (int q = 0; q < 8; q++) {
                    int k = k0 + kq + q;
                    Bs[(kq+q)*128 + o] = (og < D && k < D) ? W[(long)og * 600 + 300 + k] : 0.f;
                }
            }
        }
        __syncthreads();
#pragma unroll
        for (int kk = 0; kk < 16; kk++) {
            float4 a = *(const float4*)&As[kk*64 + ty*4];
            ulonglong2 bp0 = *(const ulonglong2*)&Bs[kk*128 + tx*4];
            ulonglong2 bp1 = *(const ulonglong2*)&Bs[kk*128 + 64 + tx*4];
            float av[4] = {a.x, a.y, a.z, a.w};
#pragma unroll
            for (int i = 0; i < 4; i++) {
                unsigned long long ad = pack_dup(av[i]);
                ffma2(acc[i][0], ad, bp0.x); ffma2(acc[i][1], ad, bp0.y);
                ffma2(acc[i][2], ad, bp1.x); ffma2(acc[i][3], ad, bp1.y);
            }
        }
        __syncthreads();
    }
#pragma unroll
    for (int i = 0; i < 4; i++) {
        int r = m0 + ty*4 + i;
#pragma unroll
        for (int j = 0; j < 4; j++) {
            float lo, hi; unpack2(acc[i][j], lo, hi);
            int ob = o0 + ((j < 2) ? (tx*4 + 2*j) : (64 + tx*4 + 2*(j-2)));
            if (ob < D)     g_vecpart[(long)r * D + ob]     = lo + __ldg(&bias[ob]);
            if (ob + 1 < D) g_vecpart[(long)r * D + ob + 1] = hi + __ldg(&bias[ob+1]);
        }
    }
}

// ---------------------------------------------------------------------------
// Kernel 2: score via warp HMMA (mma.sync m16n8k16 bf16, 2-term split).
// CTA = 128 rows, 8 warps (16 rows each). o-tiles of 64, k-chunks of 64.
// smem tiles row-stride 72 bf16 (144B) -> conflict-free ldmatrix.
// ---------------------------------------------------------------------------
#define ASTRIDE 72
// smem byte offsets
#define SA_HI 0                      // 128*72*2 = 18432
#define SA_LO 18432
#define SB_HI 36864                  // 64*72*2 = 9216
#define SB_LO 46080
#define SVPS  55296                  // 8*300*4 = 9600
#define SVS   64896                  // 300*4 = 1200
#define SSC   66096                  // 128*4 = 512
#define SMEM_SCORE 66608

__global__ __launch_bounds__(256)
void score_mma_kernel(const float* __restrict__ v)
{
    extern __shared__ char smem[];
    const uint32_t sb = smem_u32(smem);
    const int tid = threadIdx.x;
    const int wid = tid >> 5, lid = tid & 31;
    const int m0 = blockIdx.x * 128;
    const int bs0 = m0 / WL;
    const int wm = wid * 16;              // warp's row base within tile

    float* vps = (float*)(smem + SVPS);
    float* vsm = (float*)(smem + SVS);
    float* scs = (float*)(smem + SSC);

    // Preload vecpart rows (8 distinct bs per 128-row tile) and v; zero score
    for (int it = tid; it < 8 * D; it += 256) {
        int r = it / D, o = it - r * D;
        int bsg = bs0 + r;
        vps[it] = (bsg < M_VEC) ? g_vecpart[(long)bsg * D + o] : 0.f;
    }
    for (int it = tid; it < D; it += 256) vsm[it] = v[it];
    if (tid < 128) scs[tid] = 0.f;

    // Per-lane ldmatrix address offsets (element units)
    const int a_row = ((lid >> 3) & 1) * 8 + (lid & 7);
    const int a_col = (lid >> 4) * 8;
    const int b_row = (lid >> 4) * 8 + (lid & 7);
    const int b_col = ((lid >> 3) & 1) * 8;

    const uint32_t aAhi = sb + SA_HI + (uint32_t)((wm + a_row) * ASTRIDE + a_col) * 2;
    const uint32_t aAlo = sb + SA_LO + (uint32_t)((wm + a_row) * ASTRIDE + a_col) * 2;
    const uint32_t aBhi = sb + SB_HI + (uint32_t)(b_row * ASTRIDE + b_col) * 2;
    const uint32_t aBlo = sb + SB_LO + (uint32_t)(b_row * ASTRIDE + b_col) * 2;

    const int g = lid >> 2, t = lid & 3;
    const int r1 = wm + g, r2 = wm + 8 + g;
    const int bsl1 = (m0 + r1) / WL - bs0;
    const int bsl2 = (m0 + r2) / WL - bs0;

    for (int ot = 0; ot < 5; ot++) {
        const int o0 = ot * 64;
        float acc[8][4];
#pragma unroll
        for (int j = 0; j < 8; j++)
#pragma unroll
            for (int q = 0; q < 4; q++) acc[j][q] = 0.f;

        for (int c = 0; c < 5; c++) {
            const int k0 = c * 64;
            __syncthreads();   // previous chunk's ldmatrix reads done

            // Stage A hi/lo: rows 0..127, 64 k each (2 threads/row)
            {
                const int row = tid >> 1, half = tid & 1;
                const size_t soff = (size_t)(m0 + row) * DPAD + k0 + half * 32;
                const uint32_t doff = (uint32_t)(row * ASTRIDE + half * 32) * 2;
                const uint4* sh = (const uint4*)(g_seq_hi + soff);
                const uint4* sl = (const uint4*)(g_seq_lo + soff);
                uint4* dh = (uint4*)(smem + SA_HI + doff);
                uint4* dl = (uint4*)(smem + SA_LO + doff);
#pragma unroll
                for (int q = 0; q < 4; q++) { dh[q] = sh[q]; dl[q] = sl[q]; }
            }
            // Stage B hi (threads 0-127) / lo (threads 128-255): rows 0..63
            {
                const int tt = tid & 127;
                const int row = tt >> 1, half = tt & 1;
                const size_t soff = (size_t)(o0 + row) * DPAD + k0 + half * 32;
                const uint32_t doff = (uint32_t)(row * ASTRIDE + half * 32) * 2;
                if (tid < 128) {
                    const uint4* s = (const uint4*)(g_Whi + soff);
                    uint4* d = (uint4*)(smem + SB_HI + doff);
#pragma unroll
                    for (int q = 0; q < 4; q++) d[q] = s[q];
                } else {
                    const uint4* s = (const uint4*)(g_Wlo + soff);
                    uint4* d = (uint4*)(smem + SB_LO + doff);
#pragma unroll
                    for (int q = 0; q < 4; q++) d[q] = s[q];
                }
            }
            __syncthreads();

#pragma unroll
            for (int ks = 0; ks < 4; ks++) {
                const uint32_t kb = (uint32_t)(ks * 16) * 2;   // byte offset along k
                uint32_t ahi[4], alo[4];
                ldsm_x4(ahi, aAhi + kb);
                ldsm_x4(alo, aAlo + kb);
#pragma unroll
                for (int p = 0; p < 4; p++) {                  // n-tile pairs (16 o each)
                    const uint32_t nb = (uint32_t)(p * 16 * ASTRIDE) * 2;
                    uint32_t bhi[4], blo[4];
                    ldsm_x4(bhi, aBhi + nb + kb);
                    ldsm_x4(blo, aBlo + nb + kb);
                    mma16816(acc[2*p],   ahi, bhi);
                    mma16816(acc[2*p+1], ahi, bhi + 2);
                    mma16816(acc[2*p],   ahi, blo);
                    mma16816(acc[2*p+1], ahi, blo + 2);
                    mma16816(acc[2*p],   alo, bhi);
                    mma16816(acc[2*p+1], alo, bhi + 2);
                }
            }
        }

        // Epilogue for this o-tile: lin = acc + vecpart; tanh * v; reduce
        float p1 = 0.f, p2 = 0.f;
#pragma unroll
        for (int j = 0; j < 8; j++) {
            int o = o0 + j * 8 + 2 * t;
            if (o < D) {
                p1 += tanhf(acc[j][0] + vps[bsl1 * D + o]) * vsm[o];
                p2 += tanhf(acc[j][2] + vps[bsl2 * D + o]) * vsm[o];
            }
            if (o + 1 < D) {
                p1 += tanhf(acc[j][1] + vps[bsl1 * D + o + 1]) * vsm[o + 1];
                p2 += tanhf(acc[j][3] + vps[bsl2 * D + o + 1]) * vsm[o + 1];
            }
        }
        p1 += __shfl_xor_sync(0xffffffffu, p1, 1);
        p1 += __shfl_xor_sync(0xffffffffu, p1, 2);
        p2 += __shfl_xor_sync(0xffffffffu, p2, 1);
        p2 += __shfl_xor_sync(0xffffffffu, p2, 2);
        if (t == 0) { scs[r1] += p1; scs[r2] += p2; }
    }

    __syncthreads();
    if (tid < 128) g_score[m0 + tid] = scs[tid];
}

// ---------------------------------------------------------------------------
// Kernel 3: masked softmax over w (20) + weighted = alphas · seq
// ---------------------------------------------------------------------------
__global__ __launch_bounds__(128)
void softmax_weighted_kernel(const float* __restrict__ seq,
                             const int* __restrict__ masks,
                             float* __restrict__ out)
{
    const int bs = blockIdx.x;
    const int t = threadIdx.x;
    __shared__ float al[WL];

    if (t == 0) {
        float sc[WL];
        float mx = -1e30f;
#pragma unroll
        for (int w = 0; w < WL; w++) {
            float s = g_score[bs * WL + w];
            s = (masks[bs * WL + w] == 0) ? NEG_INF : s;
            sc[w] = s;
            mx = fmaxf(mx, s);
        }
        float sum = 0.f;
#pragma unroll
        for (int w = 0; w < WL; w++) {
            float e = expf(sc[w] - mx);
            al[w] = e;
            sum += e;
        }
        float inv = 1.f / sum;
#pragma unroll
        for (int w = 0; w < WL; w++) al[w] *= inv;
    }
    __syncthreads();

    const float* base = seq + (long)bs * WL * D;
    for (int d = t; d < D; d += 128) {
        float a = 0.f;
#pragma unroll
        for (int w = 0; w < WL; w++) a += al[w] * base[w * D + d];
        out[(long)bs * D + d] = a;
    }
}

// ---------------------------------------------------------------------------
extern "C" void kernel_launch(void* const* d_in, const int* in_sizes, int n_in,
                              void* d_out, int out_size)
{
    const float* seq   = (const float*)d_in[0];
    const float* vec   = (const float*)d_in[1];
    const int*   masks = (const int*)  d_in[2];
    const float* W     = (const float*)d_in[3];
    const float* bias  = (const float*)d_in[4];
    const float* v     = (const float*)d_in[5];
    float* out = (float*)d_out;

    cudaFuncSetAttribute(score_mma_kernel,
                         cudaFuncAttributeMaxDynamicSharedMemorySize, SMEM_SCORE);

    prep_w_kernel<<<(DPAD * DPAD + 255) / 256, 256>>>(W);
    prep_seq_kernel<<<(int)(((size_t)M_SEQ * (DPAD / 4) + 255) / 256), 256>>>(seq);
    vecpart_kernel<<<dim3(M_VEC / 64, 3), 256>>>(vec, W, bias);
    score_mma_kernel<<<M_SEQ / 128, 256, SMEM_SCORE>>>(v);
    softmax_weighted_kernel<<<M_VEC, 128>>>(seq, masks, out);
}

// round 5
// speedup vs baseline: 3.1051x; 1.9987x over previous
#include <cuda_runtime.h>
#include <cuda_fp16.h>
#include <math.h>
#include <stdint.h>

// Problem constants
#define BATCH 32
#define SEQ   128
#define WL    20
#define D     300
#define DPAD  320
#define M_SEQ (BATCH*SEQ*WL)      // 81920
#define M_VEC (BATCH*SEQ)         // 4096
#define NEG_INF -1000000000.0f

// Scratch (__device__ globals — no cudaMalloc allowed)
__device__ float g_vecpart[M_VEC * D];
__device__ float g_score[M_SEQ];
__device__ __align__(16) __half g_Ws[DPAD * DPAD];           // W[:, :300] fp16 padded
__device__ __align__(16) __half g_Wv[DPAD * DPAD];           // W[:, 300:] fp16 padded
__device__ __align__(16) __half g_seqh[(size_t)M_SEQ * DPAD];
__device__ __align__(16) __half g_vech[(size_t)M_VEC * DPAD];

// ---------------------------------------------------------------------------
// PTX helpers (sm_80-era — valid at plain sm_103 target)
// ---------------------------------------------------------------------------
__device__ __forceinline__ uint32_t smem_u32(const void* p) {
    uint32_t a;
    asm("{ .reg .u64 t; cvta.to.shared.u64 t, %1; cvt.u32.u64 %0, t; }" : "=r"(a) : "l"(p));
    return a;
}
__device__ __forceinline__ void ldsm_x4(uint32_t* r, uint32_t addr) {
    asm volatile("ldmatrix.sync.aligned.m8n8.x4.shared.b16 {%0,%1,%2,%3}, [%4];"
                 : "=r"(r[0]), "=r"(r[1]), "=r"(r[2]), "=r"(r[3]) : "r"(addr));
}
__device__ __forceinline__ void mma_f16(float* c, const uint32_t* a, const uint32_t* b) {
    asm volatile("mma.sync.aligned.m16n8k16.row.col.f32.f16.f16.f32 "
                 "{%0,%1,%2,%3}, {%4,%5,%6,%7}, {%8,%9}, {%0,%1,%2,%3};"
                 : "+f"(c[0]), "+f"(c[1]), "+f"(c[2]), "+f"(c[3])
                 : "r"(a[0]), "r"(a[1]), "r"(a[2]), "r"(a[3]), "r"(b[0]), "r"(b[1]));
}
__device__ __forceinline__ void cp_async16(uint32_t dst, const void* src) {
    asm volatile("cp.async.cg.shared.global [%0], [%1], 16;"
                 :: "r"(dst), "l"((size_t)__cvta_generic_to_global(src)) : "memory");
}
#define CP_COMMIT() asm volatile("cp.async.commit_group;" ::: "memory")
#define CP_WAIT0()  asm volatile("cp.async.wait_group 0;" ::: "memory")

// ---------------------------------------------------------------------------
// Prep kernels: fp16 conversion with zero padding
// ---------------------------------------------------------------------------
__global__ __launch_bounds__(256)
void prep_w_kernel(const float* __restrict__ W)
{
    int idx = blockIdx.x * 256 + threadIdx.x;
    if (idx >= DPAD * DPAD) return;
    int o = idx / DPAD, k = idx - o * DPAD;
    float ws = 0.f, wv = 0.f;
    if (o < D && k < D) {
        ws = W[(size_t)o * 600 + k];
        wv = W[(size_t)o * 600 + 300 + k];
    }
    g_Ws[idx] = __float2half_rn(ws);
    g_Wv[idx] = __float2half_rn(wv);
}

__global__ __launch_bounds__(256)
void prep_seq_kernel(const float* __restrict__ seq)
{
    size_t gid = (size_t)blockIdx.x * 256 + threadIdx.x;
    if (gid >= (size_t)M_SEQ * (DPAD / 4)) return;
    size_t row = gid / (DPAD / 4);
    int k4 = (int)(gid % (DPAD / 4));
    __half2 h0, h1;
    if (k4 < D / 4) {      // 75 exact
        float4 x = *(const float4*)(seq + row * D + (size_t)k4 * 4);
        h0 = __floats2half2_rn(x.x, x.y);
        h1 = __floats2half2_rn(x.z, x.w);
    } else {
        h0 = __floats2half2_rn(0.f, 0.f);
        h1 = h0;
    }
    *(__half2*)(g_seqh + row * DPAD + k4 * 4)     = h0;
    *(__half2*)(g_seqh + row * DPAD + k4 * 4 + 2) = h1;
}

__global__ __launch_bounds__(256)
void prep_vec_kernel(const float* __restrict__ vec)
{
    size_t gid = (size_t)blockIdx.x * 256 + threadIdx.x;
    if (gid >= (size_t)M_VEC * (DPAD / 4)) return;
    size_t row = gid / (DPAD / 4);
    int k4 = (int)(gid % (DPAD / 4));
    __half2 h0, h1;
    if (k4 < D / 4) {
        float4 x = *(const float4*)(vec + row * D + (size_t)k4 * 4);
        h0 = __floats2half2_rn(x.x, x.y);
        h1 = __floats2half2_rn(x.z, x.w);
    } else {
        h0 = __floats2half2_rn(0.f, 0.f);
        h1 = h0;
    }
    *(__half2*)(g_vech + row * DPAD + k4 * 4)     = h0;
    *(__half2*)(g_vech + row * DPAD + k4 * 4 + 2) = h1;
}

// ---------------------------------------------------------------------------
// Shared tiling constants for HMMA kernels
// CTA = 256 rows (8 warps, warp m-tile 32), k-chunk 64, o-tile 64.
// smem row stride 72 halfs (144B) -> conflict-free ldmatrix.
// ---------------------------------------------------------------------------
#define ASTRIDE 72
#define ABUF (256 * ASTRIDE * 2)     // 36864
#define BBUF (64 * ASTRIDE * 2)      // 9216
#define SM_A 0                       // two A buffers: 0, ABUF
#define SM_B (2 * ABUF)              // two B buffers: SM_B, SM_B+BBUF
#define SM_AFTER (2 * ABUF + 2 * BBUF)   // 92160

// score kernel smem
#define SVPS SM_AFTER                // 14 * 300 * 4 = 16800
#define SVS  (SVPS + 14 * D * 4)     // 108960
#define SSC  (SVS + D * 4)           // 110160 (+1024)
#define SMEM_SCORE (SSC + 1024)      // 111184

// vecpart kernel smem
#define SBIAS SM_AFTER               // 64 floats
#define SMEM_VECP (SBIAS + 256)      // 92416

// Stage one (A chunk, B chunk) pair via cp.async
__device__ __forceinline__ void stage_tiles(uint32_t sb, int buf, int m0, int o0, int k0,
                                            const __half* __restrict__ Asrc,
                                            const __half* __restrict__ Bsrc)
{
    const int tid = threadIdx.x;
    const uint32_t abase = sb + SM_A + (buf ? ABUF : 0);
    const uint32_t bbase = sb + SM_B + (buf ? BBUF : 0);
#pragma unroll
    for (int q = 0; q < 8; q++) {           // A: 2048 16B segments
        int it = tid + q * 256;
        int r = it >> 3, s = it & 7;
        cp_async16(abase + (uint32_t)(r * 144 + s * 16),
                   Asrc + (size_t)(m0 + r) * DPAD + k0 + s * 8);
    }
#pragma unroll
    for (int q = 0; q < 2; q++) {           // B: 512 16B segments
        int it = tid + q * 256;
        int r = it >> 3, s = it & 7;
        cp_async16(bbase + (uint32_t)(r * 144 + s * 16),
                   Bsrc + (size_t)(o0 + r) * DPAD + k0 + s * 8);
    }
    CP_COMMIT();
}

// ---------------------------------------------------------------------------
// Kernel: score via fp16 HMMA. grid = 320 (m-tiles of 256).
// per warp: m32 x n64 (acc0/acc1 = 2 x [8][4]).
// ---------------------------------------------------------------------------
__global__ __launch_bounds__(256, 1)
void score_mma_kernel(const float* __restrict__ v)
{
    extern __shared__ char smem[];
    const uint32_t sb = smem_u32(smem);
    const int tid = threadIdx.x;
    const int wid = tid >> 5, lid = tid & 31;
    const int m0 = blockIdx.x * 256;
    const int bs0 = m0 / WL;
    const int wm = wid * 32;

    float* vps = (float*)(smem + SVPS);
    float* vsm = (float*)(smem + SVS);
    float* scs = (float*)(smem + SSC);

    // Prefetch stage 0 (ot=0, c=0)
    stage_tiles(sb, 0, m0, 0, 0, g_seqh, g_Ws);

    // Preload vecpart rows (up to 14 distinct bs) and v; zero score
    for (int it = tid; it < 14 * D; it += 256) {
        int r = it / D, o = it - r * D;
        int bsg = bs0 + r;
        vps[it] = (bsg < M_VEC) ? g_vecpart[(size_t)bsg * D + o] : 0.f;
    }
    for (int it = tid; it < D; it += 256) vsm[it] = v[it];
    scs[tid] = 0.f;

    CP_WAIT0();
    __syncthreads();

    // ldmatrix lane addressing (proven fragment mapping from R4)
    const int a_row = ((lid >> 3) & 1) * 8 + (lid & 7);
    const int a_col = (lid >> 4) * 8;
    const int b_row = (lid >> 4) * 8 + (lid & 7);
    const int b_col = ((lid >> 3) & 1) * 8;
    const uint32_t aAoff = (uint32_t)((wm + a_row) * ASTRIDE + a_col) * 2;
    const uint32_t aBoff = (uint32_t)(b_row * ASTRIDE + b_col) * 2;

    const int g = lid >> 2, t = lid & 3;
    int rr[4], bsl[4];
    rr[0] = wm + g;      rr[1] = wm + 8 + g;
    rr[2] = wm + 16 + g; rr[3] = wm + 24 + g;
#pragma unroll
    for (int q = 0; q < 4; q++) bsl[q] = (m0 + rr[q]) / WL - bs0;

    float acc0[8][4], acc1[8][4];

    for (int i = 0; i < 25; i++) {
        const int ot = i / 5, c = i - ot * 5, buf = i & 1;

        if (c == 0) {
#pragma unroll
            for (int j = 0; j < 8; j++)
#pragma unroll
                for (int q = 0; q < 4; q++) { acc0[j][q] = 0.f; acc1[j][q] = 0.f; }
        }

        // Prefetch next stage into other buffer (overlaps with MMA below)
        if (i + 1 < 25) {
            int ni = i + 1, not_ = ni / 5, nc = ni - not_ * 5;
            stage_tiles(sb, ni & 1, m0, not_ * 64, nc * 64, g_seqh, g_Ws);
        }

        const uint32_t abase = sb + SM_A + (buf ? ABUF : 0);
        const uint32_t bbase = sb + SM_B + (buf ? BBUF : 0);
#pragma unroll
        for (int ks = 0; ks < 4; ks++) {
            const uint32_t kb = (uint32_t)ks * 32;   // 16 halfs = 32B
            uint32_t a0[4], a1[4];
            ldsm_x4(a0, abase + aAoff + kb);
            ldsm_x4(a1, abase + aAoff + kb + 16 * ASTRIDE * 2);
#pragma unroll
            for (int p = 0; p < 4; p++) {
                uint32_t b[4];
                ldsm_x4(b, bbase + aBoff + kb + (uint32_t)(p * 16 * ASTRIDE * 2));
                mma_f16(acc0[2*p],   a0, b);
                mma_f16(acc0[2*p+1], a0, b + 2);
                mma_f16(acc1[2*p],   a1, b);
                mma_f16(acc1[2*p+1], a1, b + 2);
            }
        }

        // End of o-tile: tanh(lin)*v, reduce over this tile's 64 o's
        if (c == 4) {
            const int o0 = ot * 64;
            float p[4] = {0.f, 0.f, 0.f, 0.f};
#pragma unroll
            for (int j = 0; j < 8; j++) {
                int o = o0 + j * 8 + 2 * t;
                if (o < D) {
                    float vv = vsm[o];
                    p[0] += tanhf(acc0[j][0] + vps[bsl[0] * D + o]) * vv;
                    p[1] += tanhf(acc0[j][2] + vps[bsl[1] * D + o]) * vv;
                    p[2] += tanhf(acc1[j][0] + vps[bsl[2] * D + o]) * vv;
                    p[3] += tanhf(acc1[j][2] + vps[bsl[3] * D + o]) * vv;
                }
                if (o + 1 < D) {
                    float vv = vsm[o + 1];
                    p[0] += tanhf(acc0[j][1] + vps[bsl[0] * D + o + 1]) * vv;
                    p[1] += tanhf(acc0[j][3] + vps[bsl[1] * D + o + 1]) * vv;
                    p[2] += tanhf(acc1[j][1] + vps[bsl[2] * D + o + 1]) * vv;
                    p[3] += tanhf(acc1[j][3] + vps[bsl[3] * D + o + 1]) * vv;
                }
            }
#pragma unroll
            for (int q = 0; q < 4; q++) {
                p[q] += __shfl_xor_sync(0xffffffffu, p[q], 1);
                p[q] += __shfl_xor_sync(0xffffffffu, p[q], 2);
            }
            if (t == 0) {
                scs[rr[0]] += p[0]; scs[rr[1]] += p[1];
                scs[rr[2]] += p[2]; scs[rr[3]] += p[3];
            }
        }

        CP_WAIT0();
        __syncthreads();
    }

    g_score[m0 + tid] = scs[tid];
}

// ---------------------------------------------------------------------------
// Kernel: vecpart via fp16 HMMA. grid = (16, 5): 16 m-tiles x 5 o-tiles.
// ---------------------------------------------------------------------------
__global__ __launch_bounds__(256, 1)
void vecpart_mma_kernel(const float* __restrict__ bias)
{
    extern __shared__ char smem[];
    const uint32_t sb = smem_u32(smem);
    const int tid = threadIdx.x;
    const int wid = tid >> 5, lid = tid & 31;
    const int m0 = blockIdx.x * 256;
    const int o0 = blockIdx.y * 64;
    const int wm = wid * 32;

    float* bsm = (float*)(smem + SBIAS);

    stage_tiles(sb, 0, m0, o0, 0, g_vech, g_Wv);

    if (tid < 64) bsm[tid] = (o0 + tid < D) ? bias[o0 + tid] : 0.f;

    CP_WAIT0();
    __syncthreads();

    const int a_row = ((lid >> 3) & 1) * 8 + (lid & 7);
    const int a_col = (lid >> 4) * 8;
    const int b_row = (lid >> 4) * 8 + (lid & 7);
    const int b_col = ((lid >> 3) & 1) * 8;
    const uint32_t aAoff = (uint32_t)((wm + a_row) * ASTRIDE + a_col) * 2;
    const uint32_t aBoff = (uint32_t)(b_row * ASTRIDE + b_col) * 2;

    const int g = lid >> 2, t = lid & 3;
    int rr[4];
    rr[0] = wm + g;      rr[1] = wm + 8 + g;
    rr[2] = wm + 16 + g; rr[3] = wm + 24 + g;

    float acc0[8][4], acc1[8][4];
#pragma unroll
    for (int j = 0; j < 8; j++)
#pragma unroll
        for (int q = 0; q < 4; q++) { acc0[j][q] = 0.f; acc1[j][q] = 0.f; }

    for (int c = 0; c < 5; c++) {
        const int buf = c & 1;
        if (c + 1 < 5)
            stage_tiles(sb, (c + 1) & 1, m0, o0, (c + 1) * 64, g_vech, g_Wv);

        const uint32_t abase = sb + SM_A + (buf ? ABUF : 0);
        const uint32_t bbase = sb + SM_B + (buf ? BBUF : 0);
#pragma unroll
        for (int ks = 0; ks < 4; ks++) {
            const uint32_t kb = (uint32_t)ks * 32;
            uint32_t a0[4], a1[4];
            ldsm_x4(a0, abase + aAoff + kb);
            ldsm_x4(a1, abase + aAoff + kb + 16 * ASTRIDE * 2);
#pragma unroll
            for (int p = 0; p < 4; p++) {
                uint32_t b[4];
                ldsm_x4(b, bbase + aBoff + kb + (uint32_t)(p * 16 * ASTRIDE * 2));
                mma_f16(acc0[2*p],   a0, b);
                mma_f16(acc0[2*p+1], a0, b + 2);
                mma_f16(acc1[2*p],   a1, b);
                mma_f16(acc1[2*p+1], a1, b + 2);
            }
        }

        CP_WAIT0();
        __syncthreads();
    }

    // Epilogue: vecpart[r][o] = acc + bias[o]
#pragma unroll
    for (int j = 0; j < 8; j++) {
        int oc = j * 8 + 2 * t;
        int o = o0 + oc;
        if (o < D) {
            float bb = bsm[oc];
            g_vecpart[(size_t)(m0 + rr[0]) * D + o] = acc0[j][0] + bb;
            g_vecpart[(size_t)(m0 + rr[1]) * D + o] = acc0[j][2] + bb;
            g_vecpart[(size_t)(m0 + rr[2]) * D + o] = acc1[j][0] + bb;
            g_vecpart[(size_t)(m0 + rr[3]) * D + o] = acc1[j][2] + bb;
        }
        if (o + 1 < D) {
            float bb = bsm[oc + 1];
            g_vecpart[(size_t)(m0 + rr[0]) * D + o + 1] = acc0[j][1] + bb;
            g_vecpart[(size_t)(m0 + rr[1]) * D + o + 1] = acc0[j][3] + bb;
            g_vecpart[(size_t)(m0 + rr[2]) * D + o + 1] = acc1[j][1] + bb;
            g_vecpart[(size_t)(m0 + rr[3]) * D + o + 1] = acc1[j][3] + bb;
        }
    }
}

// ---------------------------------------------------------------------------
// Kernel: masked softmax over w (20) + weighted = alphas · seq
// ---------------------------------------------------------------------------
__global__ __launch_bounds__(128)
void softmax_weighted_kernel(const float* __restrict__ seq,
                             const int* __restrict__ masks,
                             float* __restrict__ out)
{
    const int bs = blockIdx.x;
    const int t = threadIdx.x;
    __shared__ float al[WL];

    if (t == 0) {
        float sc[WL];
        float mx = -1e30f;
#pragma unroll
        for (int w = 0; w < WL; w++) {
            float s = g_score[bs * WL + w];
            s = (masks[bs * WL + w] == 0) ? NEG_INF : s;
            sc[w] = s;
            mx = fmaxf(mx, s);
        }
        float sum = 0.f;
#pragma unroll
        for (int w = 0; w < WL; w++) {
            float e = expf(sc[w] - mx);
            al[w] = e;
            sum += e;
        }
        float inv = 1.f / sum;
#pragma unroll
        for (int w = 0; w < WL; w++) al[w] *= inv;
    }
    __syncthreads();

    const float* base = seq + (size_t)bs * WL * D;
    for (int d = t; d < D; d += 128) {
        float a = 0.f;
#pragma unroll
        for (int w = 0; w < WL; w++) a += al[w] * base[w * D + d];
        out[(size_t)bs * D + d] = a;
    }
}

// ---------------------------------------------------------------------------
extern "C" void kernel_launch(void* const* d_in, const int* in_sizes, int n_in,
                              void* d_out, int out_size)
{
    const float* seq   = (const float*)d_in[0];
    const float* vec   = (const float*)d_in[1];
    const int*   masks = (const int*)  d_in[2];
    const float* W     = (const float*)d_in[3];
    const float* bias  = (const float*)d_in[4];
    const float* v     = (const float*)d_in[5];
    float* out = (float*)d_out;

    cudaFuncSetAttribute(score_mma_kernel,
                         cudaFuncAttributeMaxDynamicSharedMemorySize, SMEM_SCORE);
    cudaFuncSetAttribute(vecpart_mma_kernel,
                         cudaFuncAttributeMaxDynamicSharedMemorySize, SMEM_VECP);

    prep_w_kernel<<<(DPAD * DPAD + 255) / 256, 256>>>(W);
    prep_seq_kernel<<<(int)(((size_t)M_SEQ * (DPAD / 4) + 255) / 256), 256>>>(seq);
    prep_vec_kernel<<<(int)(((size_t)M_VEC * (DPAD / 4) + 255) / 256), 256>>>(vec);
    vecpart_mma_kernel<<<dim3(M_VEC / 256, 5), 256, SMEM_VECP>>>(bias);
    score_mma_kernel<<<M_SEQ / 256, 256, SMEM_SCORE>>>(v);
    softmax_weighted_kernel<<<M_VEC, 128>>>(seq, masks, out);
}

// round 6
// speedup vs baseline: 3.5519x; 1.1439x over previous
#include <cuda_runtime.h>
#include <cuda_fp16.h>
#include <math.h>
#include <stdint.h>

// Problem constants
#define BATCH 32
#define SEQ   128
#define WL    20
#define D     300
#define DPAD  320
#define M_SEQ (BATCH*SEQ*WL)      // 81920
#define M_VEC (BATCH*SEQ)         // 4096
#define NEG_INF -1000000000.0f

// Scratch (__device__ globals — no cudaMalloc allowed)
__device__ float g_vecpart[M_VEC * D];
__device__ float g_score[M_SEQ];
__device__ __align__(16) __half g_Ws[DPAD * DPAD];
__device__ __align__(16) __half g_Wv[DPAD * DPAD];
__device__ __align__(16) __half g_seqh[(size_t)M_SEQ * DPAD];
__device__ __align__(16) __half g_vech[(size_t)M_VEC * DPAD];

// ---------------------------------------------------------------------------
// PTX helpers (sm_80-era — valid at plain sm_103 target)
// ---------------------------------------------------------------------------
__device__ __forceinline__ uint32_t smem_u32(const void* p) {
    uint32_t a;
    asm("{ .reg .u64 t; cvta.to.shared.u64 t, %1; cvt.u32.u64 %0, t; }" : "=r"(a) : "l"(p));
    return a;
}
__device__ __forceinline__ void ldsm_x4(uint32_t* r, uint32_t addr) {
    asm volatile("ldmatrix.sync.aligned.m8n8.x4.shared.b16 {%0,%1,%2,%3}, [%4];"
                 : "=r"(r[0]), "=r"(r[1]), "=r"(r[2]), "=r"(r[3]) : "r"(addr));
}
__device__ __forceinline__ void mma_f16(float* c, const uint32_t* a, const uint32_t* b) {
    asm volatile("mma.sync.aligned.m16n8k16.row.col.f32.f16.f16.f32 "
                 "{%0,%1,%2,%3}, {%4,%5,%6,%7}, {%8,%9}, {%0,%1,%2,%3};"
                 : "+f"(c[0]), "+f"(c[1]), "+f"(c[2]), "+f"(c[3])
                 : "r"(a[0]), "r"(a[1]), "r"(a[2]), "r"(a[3]), "r"(b[0]), "r"(b[1]));
}
__device__ __forceinline__ void cp_async16(uint32_t dst, const void* src) {
    asm volatile("cp.async.cg.shared.global [%0], [%1], 16;"
                 :: "r"(dst), "l"((size_t)__cvta_generic_to_global(src)) : "memory");
}
#define CP_COMMIT() asm volatile("cp.async.commit_group;" ::: "memory")
#define CP_WAIT0()  asm volatile("cp.async.wait_group 0;" ::: "memory")

__device__ __forceinline__ float tanh_fast(float x) {
    float y;
    asm("tanh.approx.f32 %0, %1;" : "=f"(y) : "f"(x));
    return y;
}

// ---------------------------------------------------------------------------
// Prep kernels: fp16 conversion with zero padding (16B-wide stores)
// one thread = 8 consecutive k
// ---------------------------------------------------------------------------
__device__ __forceinline__ void cvt8_store(__half* dst, const float* src, int k8) {
    uint4 out;
    __half2 h[4];
    if (k8 < 37) {                    // 296/8: fully in-bounds
        float4 a = *(const float4*)(src);
        float4 b = *(const float4*)(src + 4);
        h[0] = __floats2half2_rn(a.x, a.y);
        h[1] = __floats2half2_rn(a.z, a.w);
        h[2] = __floats2half2_rn(b.x, b.y);
        h[3] = __floats2half2_rn(b.z, b.w);
    } else if (k8 == 37) {            // 296..299 valid, 300..303 pad
        float4 a = *(const float4*)(src);
        h[0] = __floats2half2_rn(a.x, a.y);
        h[1] = __floats2half2_rn(a.z, a.w);
        h[2] = __floats2half2_rn(0.f, 0.f);
        h[3] = h[2];
    } else {
        h[0] = __floats2half2_rn(0.f, 0.f);
        h[1] = h[0]; h[2] = h[0]; h[3] = h[0];
    }
    memcpy(&out, h, 16);
    *(uint4*)dst = out;
}

__global__ __launch_bounds__(256)
void prep_seq_kernel(const float* __restrict__ seq)
{
    size_t gid = (size_t)blockIdx.x * 256 + threadIdx.x;
    if (gid >= (size_t)M_SEQ * (DPAD / 8)) return;
    size_t row = gid / (DPAD / 8);
    int k8 = (int)(gid % (DPAD / 8));
    cvt8_store(g_seqh + row * DPAD + k8 * 8, seq + row * D + (size_t)k8 * 8, k8);
}

__global__ __launch_bounds__(256)
void prep_vec_kernel(const float* __restrict__ vec)
{
    size_t gid = (size_t)blockIdx.x * 256 + threadIdx.x;
    if (gid >= (size_t)M_VEC * (DPAD / 8)) return;
    size_t row = gid / (DPAD / 8);
    int k8 = (int)(gid % (DPAD / 8));
    cvt8_store(g_vech + row * DPAD + k8 * 8, vec + row * D + (size_t)k8 * 8, k8);
}

__global__ __launch_bounds__(256)
void prep_w_kernel(const float* __restrict__ W)
{
    int idx = blockIdx.x * 256 + threadIdx.x;
    if (idx >= DPAD * DPAD) return;
    int o = idx / DPAD, k = idx - o * DPAD;
    float ws = 0.f, wv = 0.f;
    if (o < D && k < D) {
        ws = W[(size_t)o * 600 + k];
        wv = W[(size_t)o * 600 + 300 + k];
    }
    g_Ws[idx] = __float2half_rn(ws);
    g_Wv[idx] = __float2half_rn(wv);
}

// ---------------------------------------------------------------------------
// Tiling: smem row stride 72 halfs (144B), conflict-free ldmatrix.
// ---------------------------------------------------------------------------
#define ASTRIDE 72

// Stage one (A rows x 64k, B 64 x 64k) pair via cp.async; ROWS in {128, 256}
template<int ROWS>
__device__ __forceinline__ void stage_tiles(uint32_t abase, uint32_t bbase,
                                            int m0, int o0, int k0,
                                            const __half* __restrict__ Asrc,
                                            const __half* __restrict__ Bsrc)
{
    const int tid = threadIdx.x;
#pragma unroll
    for (int q = 0; q < ROWS * 8 / 256; q++) {
        int it = tid + q * 256;
        int r = it >> 3, s = it & 7;
        cp_async16(abase + (uint32_t)(r * 144 + s * 16),
                   Asrc + (size_t)(m0 + r) * DPAD + k0 + s * 8);
    }
#pragma unroll
    for (int q = 0; q < 2; q++) {
        int it = tid + q * 256;
        int r = it >> 3, s = it & 7;
        cp_async16(bbase + (uint32_t)(r * 144 + s * 16),
                   Bsrc + (size_t)(o0 + r) * DPAD + k0 + s * 8);
    }
    CP_COMMIT();
}

// score kernel smem layout (256-row A)
#define ABUF (256 * ASTRIDE * 2)         // 36864
#define BBUF (64 * ASTRIDE * 2)          // 9216
#define SM_A 0
#define SM_B (2 * ABUF)                  // 73728
#define SM_AFTER (2 * ABUF + 2 * BBUF)   // 92160
#define SVPS SM_AFTER
#define SVS  (SVPS + 14 * D * 4)         // 108960
#define SSC  (SVS + D * 4)               // 110160
#define SMEM_SCORE (SSC + 1024)          // 111184

// vecpart kernel smem layout (128-row A)
#define VABUF (128 * ASTRIDE * 2)        // 18432
#define VSM_B (2 * VABUF)                // 36864
#define VSM_BIAS (2 * VABUF + 2 * BBUF)  // 55296
#define SMEM_VECP (VSM_BIAS + 256)       // 55552

// ---------------------------------------------------------------------------
// Kernel: score via fp16 HMMA. grid = 320 (m-tiles of 256), 8 warps (m32 each).
// ---------------------------------------------------------------------------
__global__ __launch_bounds__(256, 1)
void score_mma_kernel(const float* __restrict__ v)
{
    extern __shared__ char smem[];
    const uint32_t sb = smem_u32(smem);
    const int tid = threadIdx.x;
    const int wid = tid >> 5, lid = tid & 31;
    const int m0 = blockIdx.x * 256;
    const int bs0 = m0 / WL;
    const int wm = wid * 32;

    float* vps = (float*)(smem + SVPS);
    float* vsm = (float*)(smem + SVS);
    float* scs = (float*)(smem + SSC);

    stage_tiles<256>(sb + SM_A, sb + SM_B, m0, 0, 0, g_seqh, g_Ws);

    for (int it = tid; it < 14 * D; it += 256) {
        int r = it / D, o = it - r * D;
        int bsg = bs0 + r;
        vps[it] = (bsg < M_VEC) ? g_vecpart[(size_t)bsg * D + o] : 0.f;
    }
    for (int it = tid; it < D; it += 256) vsm[it] = v[it];
    scs[tid] = 0.f;

    CP_WAIT0();
    __syncthreads();

    const int a_row = ((lid >> 3) & 1) * 8 + (lid & 7);
    const int a_col = (lid >> 4) * 8;
    const int b_row = (lid >> 4) * 8 + (lid & 7);
    const int b_col = ((lid >> 3) & 1) * 8;
    const uint32_t aAoff = (uint32_t)((wm + a_row) * ASTRIDE + a_col) * 2;
    const uint32_t aBoff = (uint32_t)(b_row * ASTRIDE + b_col) * 2;

    const int g = lid >> 2, t = lid & 3;
    int rr[4], bsl[4];
    rr[0] = wm + g;      rr[1] = wm + 8 + g;
    rr[2] = wm + 16 + g; rr[3] = wm + 24 + g;
#pragma unroll
    for (int q = 0; q < 4; q++) bsl[q] = (m0 + rr[q]) / WL - bs0;

    float acc0[8][4], acc1[8][4];

    for (int i = 0; i < 25; i++) {
        const int ot = i / 5, c = i - ot * 5, buf = i & 1;

        if (c == 0) {
#pragma unroll
            for (int j = 0; j < 8; j++)
#pragma unroll
                for (int q = 0; q < 4; q++) { acc0[j][q] = 0.f; acc1[j][q] = 0.f; }
        }

        if (i + 1 < 25) {
            int ni = i + 1, not_ = ni / 5, nc = ni - not_ * 5;
            stage_tiles<256>(sb + SM_A + ((ni & 1) ? ABUF : 0),
                             sb + SM_B + ((ni & 1) ? BBUF : 0),
                             m0, not_ * 64, nc * 64, g_seqh, g_Ws);
        }

        const uint32_t abase = sb + SM_A + (buf ? ABUF : 0);
        const uint32_t bbase = sb + SM_B + (buf ? BBUF : 0);
#pragma unroll
        for (int ks = 0; ks < 4; ks++) {
            const uint32_t kb = (uint32_t)ks * 32;
            uint32_t a0[4], a1[4];
            ldsm_x4(a0, abase + aAoff + kb);
            ldsm_x4(a1, abase + aAoff + kb + 16 * ASTRIDE * 2);
#pragma unroll
            for (int p = 0; p < 4; p++) {
                uint32_t b[4];
                ldsm_x4(b, bbase + aBoff + kb + (uint32_t)(p * 16 * ASTRIDE * 2));
                mma_f16(acc0[2*p],   a0, b);
                mma_f16(acc0[2*p+1], a0, b + 2);
                mma_f16(acc1[2*p],   a1, b);
                mma_f16(acc1[2*p+1], a1, b + 2);
            }
        }

        if (c == 4) {
            const int o0t = ot * 64;
            float p[4] = {0.f, 0.f, 0.f, 0.f};
            const float* vp0 = vps + bsl[0] * D;
            const float* vp1 = vps + bsl[1] * D;
            const float* vp2 = vps + bsl[2] * D;
            const float* vp3 = vps + bsl[3] * D;
            if (o0t + 64 <= D) {
                // full tile, no bounds checks
#pragma unroll
                for (int j = 0; j < 8; j++) {
                    int o = o0t + j * 8 + 2 * t;
                    float v0 = vsm[o], v1 = vsm[o + 1];
                    p[0] += tanh_fast(acc0[j][0] + vp0[o]) * v0
                          + tanh_fast(acc0[j][1] + vp0[o + 1]) * v1;
                    p[1] += tanh_fast(acc0[j][2] + vp1[o]) * v0
                          + tanh_fast(acc0[j][3] + vp1[o + 1]) * v1;
                    p[2] += tanh_fast(acc1[j][0] + vp2[o]) * v0
                          + tanh_fast(acc1[j][1] + vp2[o + 1]) * v1;
                    p[3] += tanh_fast(acc1[j][2] + vp3[o]) * v0
                          + tanh_fast(acc1[j][3] + vp3[o + 1]) * v1;
                }
            } else {
#pragma unroll
                for (int j = 0; j < 8; j++) {
                    int o = o0t + j * 8 + 2 * t;
                    if (o < D) {
                        float v0 = vsm[o];
                        p[0] += tanh_fast(acc0[j][0] + vp0[o]) * v0;
                        p[1] += tanh_fast(acc0[j][2] + vp1[o]) * v0;
                        p[2] += tanh_fast(acc1[j][0] + vp2[o]) * v0;
                        p[3] += tanh_fast(acc1[j][2] + vp3[o]) * v0;
                    }
                    if (o + 1 < D) {
                        float v1 = vsm[o + 1];
                        p[0] += tanh_fast(acc0[j][1] + vp0[o + 1]) * v1;
                        p[1] += tanh_fast(acc0[j][3] + vp1[o + 1]) * v1;
                        p[2] += tanh_fast(acc1[j][1] + vp2[o + 1]) * v1;
                        p[3] += tanh_fast(acc1[j][3] + vp3[o + 1]) * v1;
                    }
                }
            }
#pragma unroll
            for (int q = 0; q < 4; q++) {
                p[q] += __shfl_xor_sync(0xffffffffu, p[q], 1);
                p[q] += __shfl_xor_sync(0xffffffffu, p[q], 2);
            }
            if (t == 0) {
                scs[rr[0]] += p[0]; scs[rr[1]] += p[1];
                scs[rr[2]] += p[2]; scs[rr[3]] += p[3];
            }
        }

        CP_WAIT0();
        __syncthreads();
    }

    g_score[m0 + tid] = scs[tid];
}

// ---------------------------------------------------------------------------
// Kernel: vecpart via fp16 HMMA. grid = (32, 5): m-tiles of 128, 8 warps (m16).
// ---------------------------------------------------------------------------
__global__ __launch_bounds__(256, 2)
void vecpart_mma_kernel(const float* __restrict__ bias)
{
    extern __shared__ char smem[];
    const uint32_t sb = smem_u32(smem);
    const int tid = threadIdx.x;
    const int wid = tid >> 5, lid = tid & 31;
    const int m0 = blockIdx.x * 128;
    const int o0 = blockIdx.y * 64;
    const int wm = wid * 16;

    float* bsm = (float*)(smem + VSM_BIAS);

    stage_tiles<128>(sb, sb + VSM_B, m0, o0, 0, g_vech, g_Wv);

    if (tid < 64) bsm[tid] = (o0 + tid < D) ? bias[o0 + tid] : 0.f;

    CP_WAIT0();
    __syncthreads();

    const int a_row = ((lid >> 3) & 1) * 8 + (lid & 7);
    const int a_col = (lid >> 4) * 8;
    const int b_row = (lid >> 4) * 8 + (lid & 7);
    const int b_col = ((lid >> 3) & 1) * 8;
    const uint32_t aAoff = (uint32_t)((wm + a_row) * ASTRIDE + a_col) * 2;
    const uint32_t aBoff = (uint32_t)(b_row * ASTRIDE + b_col) * 2;

    const int g = lid >> 2, t = lid & 3;
    const int r0 = wm + g, r1 = wm + 8 + g;

    float acc[8][4];
#pragma unroll
    for (int j = 0; j < 8; j++)
#pragma unroll
        for (int q = 0; q < 4; q++) acc[j][q] = 0.f;

    for (int c = 0; c < 5; c++) {
        const int buf = c & 1;
        if (c + 1 < 5)
            stage_tiles<128>(sb + (((c + 1) & 1) ? VABUF : 0),
                             sb + VSM_B + (((c + 1) & 1) ? BBUF : 0),
                             m0, o0, (c + 1) * 64, g_vech, g_Wv);

        const uint32_t abase = sb + (buf ? VABUF : 0);
        const uint32_t bbase = sb + VSM_B + (buf ? BBUF : 0);
#pragma unroll
        for (int ks = 0; ks < 4; ks++) {
            const uint32_t kb = (uint32_t)ks * 32;
            uint32_t a0[4];
            ldsm_x4(a0, abase + aAoff + kb);
#pragma unroll
            for (int p = 0; p < 4; p++) {
                uint32_t b[4];
                ldsm_x4(b, bbase + aBoff + kb + (uint32_t)(p * 16 * ASTRIDE * 2));
                mma_f16(acc[2*p],   a0, b);
                mma_f16(acc[2*p+1], a0, b + 2);
            }
        }

        CP_WAIT0();
        __syncthreads();
    }

#pragma unroll
    for (int j = 0; j < 8; j++) {
        int oc = j * 8 + 2 * t;
        int o = o0 + oc;
        if (o < D) {
            float bb = bsm[oc];
            g_vecpart[(size_t)(m0 + r0) * D + o] = acc[j][0] + bb;
            g_vecpart[(size_t)(m0 + r1) * D + o] = acc[j][2] + bb;
        }
        if (o + 1 < D) {
            float bb = bsm[oc + 1];
            g_vecpart[(size_t)(m0 + r0) * D + o + 1] = acc[j][1] + bb;
            g_vecpart[(size_t)(m0 + r1) * D + o + 1] = acc[j][3] + bb;
        }
    }
}

// ---------------------------------------------------------------------------
// Kernel: masked softmax over w (20) + weighted = alphas · seq
// ---------------------------------------------------------------------------
__global__ __launch_bounds__(128)
void softmax_weighted_kernel(const float* __restrict__ seq,
                             const int* __restrict__ masks,
                             float* __restrict__ out)
{
    const int bs = blockIdx.x;
    const int t = threadIdx.x;
    __shared__ float al[WL];

    if (t == 0) {
        float sc[WL];
        float mx = -1e30f;
#pragma unroll
        for (int w = 0; w < WL; w++) {
            float s = g_score[bs * WL + w];
            s = (masks[bs * WL + w] == 0) ? NEG_INF : s;
            sc[w] = s;
            mx = fmaxf(mx, s);
        }
        float sum = 0.f;
#pragma unroll
        for (int w = 0; w < WL; w++) {
            float e = expf(sc[w] - mx);
            al[w] = e;
            sum += e;
        }
        float inv = 1.f / sum;
#pragma unroll
        for (int w = 0; w < WL; w++) al[w] *= inv;
    }
    __syncthreads();

    const float* base = seq + (size_t)bs * WL * D;
    for (int d = t; d < D; d += 128) {
        float a = 0.f;
#pragma unroll
        for (int w = 0; w < WL; w++) a += al[w] * base[w * D + d];
        out[(size_t)bs * D + d] = a;
    }
}

// ---------------------------------------------------------------------------
extern "C" void kernel_launch(void* const* d_in, const int* in_sizes, int n_in,
                              void* d_out, int out_size)
{
    const float* seq   = (const float*)d_in[0];
    const float* vec   = (const float*)d_in[1];
    const int*   masks = (const int*)  d_in[2];
    const float* W     = (const float*)d_in[3];
    const float* bias  = (const float*)d_in[4];
    const float* v     = (const float*)d_in[5];
    float* out = (float*)d_out;

    cudaFuncSetAttribute(score_mma_kernel,
                         cudaFuncAttributeMaxDynamicSharedMemorySize, SMEM_SCORE);
    cudaFuncSetAttribute(vecpart_mma_kernel,
                         cudaFuncAttributeMaxDynamicSharedMemorySize, SMEM_VECP);

    prep_w_kernel<<<(DPAD * DPAD + 255) / 256, 256>>>(W);
    prep_seq_kernel<<<(int)(((size_t)M_SEQ * (DPAD / 8) + 255) / 256), 256>>>(seq);
    prep_vec_kernel<<<(int)(((size_t)M_VEC * (DPAD / 8) + 255) / 256), 256>>>(vec);
    vecpart_mma_kernel<<<dim3(M_VEC / 128, 5), 256, SMEM_VECP>>>(bias);
    score_mma_kernel<<<M_SEQ / 256, 256, SMEM_SCORE>>>(v);
    softmax_weighted_kernel<<<M_VEC, 128>>>(seq, masks, out);
}

// round 7
// speedup vs baseline: 4.5129x; 1.2706x over previous
#include <cuda_runtime.h>
#include <cuda_fp16.h>
#include <math.h>
#include <stdint.h>

// Problem constants
#define BATCH 32
#define SEQ   128
#define WL    20
#define D     300
#define DPAD  320
#define M_SEQ (BATCH*SEQ*WL)      // 81920
#define M_VEC (BATCH*SEQ)         // 4096
#define NEG_INF -1000000000.0f

// Scratch (__device__ globals — no cudaMalloc allowed)
__device__ float g_vecpart[M_VEC * D];
__device__ float g_part[5 * M_SEQ];          // partial scores per o-part
__device__ __align__(16) __half g_Ws[DPAD * DPAD];
__device__ __align__(16) __half g_Wv[DPAD * DPAD];
__device__ __align__(16) __half g_seqh[(size_t)M_SEQ * DPAD];
__device__ __align__(16) __half g_vech[(size_t)M_VEC * DPAD];

// ---------------------------------------------------------------------------
// PTX helpers (sm_80-era — valid at plain sm_103 target)
// ---------------------------------------------------------------------------
__device__ __forceinline__ uint32_t smem_u32(const void* p) {
    uint32_t a;
    asm("{ .reg .u64 t; cvta.to.shared.u64 t, %1; cvt.u32.u64 %0, t; }" : "=r"(a) : "l"(p));
    return a;
}
__device__ __forceinline__ void ldsm_x4(uint32_t* r, uint32_t addr) {
    asm volatile("ldmatrix.sync.aligned.m8n8.x4.shared.b16 {%0,%1,%2,%3}, [%4];"
                 : "=r"(r[0]), "=r"(r[1]), "=r"(r[2]), "=r"(r[3]) : "r"(addr));
}
__device__ __forceinline__ void mma_f16(float* c, const uint32_t* a, const uint32_t* b) {
    asm volatile("mma.sync.aligned.m16n8k16.row.col.f32.f16.f16.f32 "
                 "{%0,%1,%2,%3}, {%4,%5,%6,%7}, {%8,%9}, {%0,%1,%2,%3};"
                 : "+f"(c[0]), "+f"(c[1]), "+f"(c[2]), "+f"(c[3])
                 : "r"(a[0]), "r"(a[1]), "r"(a[2]), "r"(a[3]), "r"(b[0]), "r"(b[1]));
}
__device__ __forceinline__ void cp_async16(uint32_t dst, const void* src) {
    asm volatile("cp.async.cg.shared.global [%0], [%1], 16;"
                 :: "r"(dst), "l"((size_t)__cvta_generic_to_global(src)) : "memory");
}
#define CP_COMMIT() asm volatile("cp.async.commit_group;" ::: "memory")
#define CP_WAIT0()  asm volatile("cp.async.wait_group 0;" ::: "memory")

__device__ __forceinline__ float tanh_fast(float x) {
    float y;
    asm("tanh.approx.f32 %0, %1;" : "=f"(y) : "f"(x));
    return y;
}

// ---------------------------------------------------------------------------
// Prep kernels: fp16 conversion with zero padding (16B-wide stores)
// ---------------------------------------------------------------------------
__device__ __forceinline__ void cvt8_store(__half* dst, const float* src, int k8) {
    uint4 out;
    __half2 h[4];
    if (k8 < 37) {
        float4 a = *(const float4*)(src);
        float4 b = *(const float4*)(src + 4);
        h[0] = __floats2half2_rn(a.x, a.y);
        h[1] = __floats2half2_rn(a.z, a.w);
        h[2] = __floats2half2_rn(b.x, b.y);
        h[3] = __floats2half2_rn(b.z, b.w);
    } else if (k8 == 37) {
        float4 a = *(const float4*)(src);
        h[0] = __floats2half2_rn(a.x, a.y);
        h[1] = __floats2half2_rn(a.z, a.w);
        h[2] = __floats2half2_rn(0.f, 0.f);
        h[3] = h[2];
    } else {
        h[0] = __floats2half2_rn(0.f, 0.f);
        h[1] = h[0]; h[2] = h[0]; h[3] = h[0];
    }
    memcpy(&out, h, 16);
    *(uint4*)dst = out;
}

__global__ __launch_bounds__(256)
void prep_seq_kernel(const float* __restrict__ seq)
{
    size_t gid = (size_t)blockIdx.x * 256 + threadIdx.x;
    if (gid >= (size_t)M_SEQ * (DPAD / 8)) return;
    size_t row = gid / (DPAD / 8);
    int k8 = (int)(gid % (DPAD / 8));
    cvt8_store(g_seqh + row * DPAD + k8 * 8, seq + row * D + (size_t)k8 * 8, k8);
}

__global__ __launch_bounds__(256)
void prep_vec_kernel(const float* __restrict__ vec)
{
    size_t gid = (size_t)blockIdx.x * 256 + threadIdx.x;
    if (gid >= (size_t)M_VEC * (DPAD / 8)) return;
    size_t row = gid / (DPAD / 8);
    int k8 = (int)(gid % (DPAD / 8));
    cvt8_store(g_vech + row * DPAD + k8 * 8, vec + row * D + (size_t)k8 * 8, k8);
}

__global__ __launch_bounds__(256)
void prep_w_kernel(const float* __restrict__ W)
{
    int idx = blockIdx.x * 256 + threadIdx.x;
    if (idx >= DPAD * DPAD) return;
    int o = idx / DPAD, k = idx - o * DPAD;
    float ws = 0.f, wv = 0.f;
    if (o < D && k < D) {
        ws = W[(size_t)o * 600 + k];
        wv = W[(size_t)o * 600 + 300 + k];
    }
    g_Ws[idx] = __float2half_rn(ws);
    g_Wv[idx] = __float2half_rn(wv);
}

// ---------------------------------------------------------------------------
// Tiling: smem row stride 72 halfs (144B), conflict-free ldmatrix.
// ---------------------------------------------------------------------------
#define ASTRIDE 72

template<int ROWS, int THREADS>
__device__ __forceinline__ void stage_tiles(uint32_t abase, uint32_t bbase,
                                            int m0, int o0, int k0,
                                            const __half* __restrict__ Asrc,
                                            const __half* __restrict__ Bsrc)
{
    const int tid = threadIdx.x;
#pragma unroll
    for (int q = 0; q < ROWS * 8 / THREADS; q++) {
        int it = tid + q * THREADS;
        int r = it >> 3, s = it & 7;
        cp_async16(abase + (uint32_t)(r * 144 + s * 16),
                   Asrc + (size_t)(m0 + r) * DPAD + k0 + s * 8);
    }
#pragma unroll
    for (int q = 0; q < 512 / THREADS; q++) {
        int it = tid + q * THREADS;
        int r = it >> 3, s = it & 7;
        cp_async16(bbase + (uint32_t)(r * 144 + s * 16),
                   Bsrc + (size_t)(o0 + r) * DPAD + k0 + s * 8);
    }
    CP_COMMIT();
}

// score kernel smem layout (128-row A, 64-o B)
#define ABUF (128 * ASTRIDE * 2)         // 18432
#define BBUF (64 * ASTRIDE * 2)          // 9216
#define SM_A 0
#define SM_B (2 * ABUF)                  // 36864
#define SVPS (2 * ABUF + 2 * BBUF)       // 55296: 8 bs-rows x 64 o x fp32 = 2048
#define SVS  (SVPS + 8 * 64 * 4)         // 57344: 64 x fp32
#define SMEM_SCORE (SVS + 256)           // 57600

// vecpart kernel smem layout (64-row A)
#define VABUF (64 * ASTRIDE * 2)         // 9216
#define VSM_B (2 * VABUF)                // 18432
#define VSM_BIAS (2 * VABUF + 2 * BBUF)  // 36864
#define SMEM_VECP (VSM_BIAS + 256)       // 37120

// ---------------------------------------------------------------------------
// Kernel: partial score via fp16 HMMA.
// grid = (640 m-tiles of 128, 5 o-parts of 64). 8 warps, warp tile m16 x n64.
// Writes g_part[opart][m] (no cross-o accumulation needed: post-tanh sum
// over o is linear, so partials sum in the softmax kernel).
// ---------------------------------------------------------------------------
__global__ __launch_bounds__(256, 2)
void score_mma_kernel(const float* __restrict__ v)
{
    extern __shared__ char smem[];
    const uint32_t sb = smem_u32(smem);
    const int tid = threadIdx.x;
    const int wid = tid >> 5, lid = tid & 31;
    const int m0 = blockIdx.x * 128;
    const int o0 = blockIdx.y * 64;
    const int bs0 = m0 / WL;
    const int wm = wid * 16;

    float* vps = (float*)(smem + SVPS);   // [8][64]
    float* vsm = (float*)(smem + SVS);    // [64]

    stage_tiles<128, 256>(sb + SM_A, sb + SM_B, m0, o0, 0, g_seqh, g_Ws);

    // vecpart slice (8 bs-rows x this o-part) and v slice; pad with zeros
    for (int it = tid; it < 8 * 64; it += 256) {
        int r = it >> 6, oc = it & 63;
        int bsg = bs0 + r, o = o0 + oc;
        vps[it] = (bsg < M_VEC && o < D) ? g_vecpart[(size_t)bsg * D + o] : 0.f;
    }
    if (tid < 64) vsm[tid] = (o0 + tid < D) ? v[o0 + tid] : 0.f;

    CP_WAIT0();
    __syncthreads();

    const int a_row = ((lid >> 3) & 1) * 8 + (lid & 7);
    const int a_col = (lid >> 4) * 8;
    const int b_row = (lid >> 4) * 8 + (lid & 7);
    const int b_col = ((lid >> 3) & 1) * 8;
    const uint32_t aAoff = (uint32_t)((wm + a_row) * ASTRIDE + a_col) * 2;
    const uint32_t aBoff = (uint32_t)(b_row * ASTRIDE + b_col) * 2;

    const int g = lid >> 2, t = lid & 3;
    const int r0 = wm + g, r1 = wm + 8 + g;
    const int bsl0 = (m0 + r0) / WL - bs0;
    const int bsl1 = (m0 + r1) / WL - bs0;

    float acc[8][4];
#pragma unroll
    for (int j = 0; j < 8; j++)
#pragma unroll
        for (int q = 0; q < 4; q++) acc[j][q] = 0.f;

    for (int c = 0; c < 5; c++) {
        const int buf = c & 1;
        if (c + 1 < 5)
            stage_tiles<128, 256>(sb + SM_A + (((c + 1) & 1) ? ABUF : 0),
                                  sb + SM_B + (((c + 1) & 1) ? BBUF : 0),
                                  m0, o0, (c + 1) * 64, g_seqh, g_Ws);

        const uint32_t abase = sb + SM_A + (buf ? ABUF : 0);
        const uint32_t bbase = sb + SM_B + (buf ? BBUF : 0);
#pragma unroll
        for (int ks = 0; ks < 4; ks++) {
            const uint32_t kb = (uint32_t)ks * 32;
            uint32_t a0[4];
            ldsm_x4(a0, abase + aAoff + kb);
#pragma unroll
            for (int p = 0; p < 4; p++) {
                uint32_t b[4];
                ldsm_x4(b, bbase + aBoff + kb + (uint32_t)(p * 16 * ASTRIDE * 2));
                mma_f16(acc[2*p],   a0, b);
                mma_f16(acc[2*p+1], a0, b + 2);
            }
        }

        CP_WAIT0();
        __syncthreads();
    }

    // Epilogue: branch-free (padded o contributes tanh(0)*0 = 0)
    float p0 = 0.f, p1 = 0.f;
    const float* vp0 = vps + bsl0 * 64;
    const float* vp1 = vps + bsl1 * 64;
#pragma unroll
    for (int j = 0; j < 8; j++) {
        int oc = j * 8 + 2 * t;
        float v0 = vsm[oc], v1 = vsm[oc + 1];
        p0 += tanh_fast(acc[j][0] + vp0[oc]) * v0
            + tanh_fast(acc[j][1] + vp0[oc + 1]) * v1;
        p1 += tanh_fast(acc[j][2] + vp1[oc]) * v0
            + tanh_fast(acc[j][3] + vp1[oc + 1]) * v1;
    }
    p0 += __shfl_xor_sync(0xffffffffu, p0, 1);
    p0 += __shfl_xor_sync(0xffffffffu, p0, 2);
    p1 += __shfl_xor_sync(0xffffffffu, p1, 1);
    p1 += __shfl_xor_sync(0xffffffffu, p1, 2);
    if (t == 0) {
        float* dst = g_part + (size_t)blockIdx.y * M_SEQ + m0;
        dst[r0] = p0;
        dst[r1] = p1;
    }
}

// ---------------------------------------------------------------------------
// Kernel: vecpart via fp16 HMMA. grid = (64, 5): m-tiles of 64, 4 warps (m16).
// ---------------------------------------------------------------------------
__global__ __launch_bounds__(128, 4)
void vecpart_mma_kernel(const float* __restrict__ bias)
{
    extern __shared__ char smem[];
    const uint32_t sb = smem_u32(smem);
    const int tid = threadIdx.x;
    const int wid = tid >> 5, lid = tid & 31;
    const int m0 = blockIdx.x * 64;
    const int o0 = blockIdx.y * 64;
    const int wm = wid * 16;

    float* bsm = (float*)(smem + VSM_BIAS);

    stage_tiles<64, 128>(sb, sb + VSM_B, m0, o0, 0, g_vech, g_Wv);

    if (tid < 64) bsm[tid] = (o0 + tid < D) ? bias[o0 + tid] : 0.f;

    CP_WAIT0();
    __syncthreads();

    const int a_row = ((lid >> 3) & 1) * 8 + (lid & 7);
    const int a_col = (lid >> 4) * 8;
    const int b_row = (lid >> 4) * 8 + (lid & 7);
    const int b_col = ((lid >> 3) & 1) * 8;
    const uint32_t aAoff = (uint32_t)((wm + a_row) * ASTRIDE + a_col) * 2;
    const uint32_t aBoff = (uint32_t)(b_row * ASTRIDE + b_col) * 2;

    const int g = lid >> 2, t = lid & 3;
    const int r0 = wm + g, r1 = wm + 8 + g;

    float acc[8][4];
#pragma unroll
    for (int j = 0; j < 8; j++)
#pragma unroll
        for (int q = 0; q < 4; q++) acc[j][q] = 0.f;

    for (int c = 0; c < 5; c++) {
        const int buf = c & 1;
        if (c + 1 < 5)
            stage_tiles<64, 128>(sb + (((c + 1) & 1) ? VABUF : 0),
                                 sb + VSM_B + (((c + 1) & 1) ? BBUF : 0),
                                 m0, o0, (c + 1) * 64, g_vech, g_Wv);

        const uint32_t abase = sb + (buf ? VABUF : 0);
        const uint32_t bbase = sb + VSM_B + (buf ? BBUF : 0);
#pragma unroll
        for (int ks = 0; ks < 4; ks++) {
            const uint32_t kb = (uint32_t)ks * 32;
            uint32_t a0[4];
            ldsm_x4(a0, abase + aAoff + kb);
#pragma unroll
            for (int p = 0; p < 4; p++) {
                uint32_t b[4];
                ldsm_x4(b, bbase + aBoff + kb + (uint32_t)(p * 16 * ASTRIDE * 2));
                mma_f16(acc[2*p],   a0, b);
                mma_f16(acc[2*p+1], a0, b + 2);
            }
        }

        CP_WAIT0();
        __syncthreads();
    }

#pragma unroll
    for (int j = 0; j < 8; j++) {
        int oc = j * 8 + 2 * t;
        int o = o0 + oc;
        if (o < D) {
            float bb = bsm[oc];
            g_vecpart[(size_t)(m0 + r0) * D + o] = acc[j][0] + bb;
            g_vecpart[(size_t)(m0 + r1) * D + o] = acc[j][2] + bb;
        }
        if (o + 1 < D) {
            float bb = bsm[oc + 1];
            g_vecpart[(size_t)(m0 + r0) * D + o + 1] = acc[j][1] + bb;
            g_vecpart[(size_t)(m0 + r1) * D + o + 1] = acc[j][3] + bb;
        }
    }
}

// ---------------------------------------------------------------------------
// Kernel: sum partials -> masked softmax over w (20) + weighted = alphas · seq
// ---------------------------------------------------------------------------
__global__ __launch_bounds__(128)
void softmax_weighted_kernel(const float* __restrict__ seq,
                             const int* __restrict__ masks,
                             float* __restrict__ out)
{
    const int bs = blockIdx.x;
    const int t = threadIdx.x;
    __shared__ float al[WL];

    if (t < 32) {
        float s = -1e30f;
        if (t < WL) {
            s = 0.f;
#pragma unroll
            for (int p = 0; p < 5; p++)
                s += g_part[(size_t)p * M_SEQ + bs * WL + t];
            if (masks[bs * WL + t] == 0) s = NEG_INF;
        }
        float mx = s;
#pragma unroll
        for (int off = 16; off > 0; off >>= 1)
            mx = fmaxf(mx, __shfl_xor_sync(0xffffffffu, mx, off));
        float e = (t < WL) ? expf(s - mx) : 0.f;
        float sum = e;
#pragma unroll
        for (int off = 16; off > 0; off >>= 1)
            sum += __shfl_xor_sync(0xffffffffu, sum, off);
        if (t < WL) al[t] = e / sum;
    }
    __syncthreads();

    const float* base = seq + (size_t)bs * WL * D;
    for (int d = t; d < D; d += 128) {
        float a = 0.f;
#pragma unroll
        for (int w = 0; w < WL; w++) a += al[w] * base[w * D + d];
        out[(size_t)bs * D + d] = a;
    }
}

// ---------------------------------------------------------------------------
extern "C" void kernel_launch(void* const* d_in, const int* in_sizes, int n_in,
                              void* d_out, int out_size)
{
    const float* seq   = (const float*)d_in[0];
    const float* vec   = (const float*)d_in[1];
    const int*   masks = (const int*)  d_in[2];
    const float* W     = (const float*)d_in[3];
    const float* bias  = (const float*)d_in[4];
    const float* v     = (const float*)d_in[5];
    float* out = (float*)d_out;

    cudaFuncSetAttribute(score_mma_kernel,
                         cudaFuncAttributeMaxDynamicSharedMemorySize, SMEM_SCORE);
    cudaFuncSetAttribute(vecpart_mma_kernel,
                         cudaFuncAttributeMaxDynamicSharedMemorySize, SMEM_VECP);

    prep_w_kernel<<<(DPAD * DPAD + 255) / 256, 256>>>(W);
    prep_seq_kernel<<<(int)(((size_t)M_SEQ * (DPAD / 8) + 255) / 256), 256>>>(seq);
    prep_vec_kernel<<<(int)(((size_t)M_VEC * (DPAD / 8) + 255) / 256), 256>>>(vec);
    vecpart_mma_kernel<<<dim3(M_VEC / 64, 5), 128, SMEM_VECP>>>(bias);
    score_mma_kernel<<<dim3(M_SEQ / 128, 5), 256, SMEM_SCORE>>>(v);
    softmax_weighted_kernel<<<M_VEC, 128>>>(seq, masks, out);
}